// round 1
// baseline (speedup 1.0000x reference)
#include <cuda_runtime.h>

#define CC    1024   // in channels (= K for projections)
#define TT    1024   // tokens = H*W
#define OUT_C 2048
#define NB    8
#define NH    32
#define HD    64

// ---------------- scratch (static device globals; no runtime allocation) ----
// g_qkv[s][w][b][t][o]: s = source (0=cnn,1=vit), w = 0:Q 1:K 2:V
__device__ float g_qkv[2][3][NB][TT][OUT_C];
__device__ float g_att[2][NB][TT][OUT_C];   // dir 0 = attended_vit, 1 = attended_cnn
__device__ float g_r[NB * TT][OUT_C];       // after mix + LayerNorm
__device__ float g_fc[NB * TT][OUT_C];      // FC output before final transpose

// ---------------- projection GEMM: Y[t][o] = sum_c X[c][t] * W[o][c] + b[o] --
// X is stored [C][T] (channel-major), which is exactly the k-major A layout a
// classic SGEMM wants: A tile loads are coalesced along t and land in shared
// without a transpose.
__global__ __launch_bounds__(256, 2) void proj_gemm(
    const float* __restrict__ xc, const float* __restrict__ xv,
    const float* __restrict__ Wq, const float* __restrict__ bq,
    const float* __restrict__ Wk, const float* __restrict__ bk,
    const float* __restrict__ Wv, const float* __restrict__ bv)
{
    int z = blockIdx.z;
    int w  = z % 3;
    int sb = z / 3;
    int s = sb >> 3, b = sb & 7;
    const float* X  = (s == 0 ? xc : xv) + (size_t)b * CC * TT;      // [C][T]
    const float* Wp = (w == 0) ? Wq : ((w == 1) ? Wk : Wv);          // [OUT][C]
    const float* bp = (w == 0) ? bq : ((w == 1) ? bk : bv);
    float* Cout = &g_qkv[s][w][b][0][0];

    __shared__ float As[8][128];
    __shared__ float Bs[8][132];   // pad 132 -> conflict-free transpose stores

    int tid = threadIdx.x;
    int tx = tid & 15, ty = tid >> 4;
    int m0 = blockIdx.y * 128;
    int n0 = blockIdx.x * 128;

    float acc[8][8] = {};

    int a_k = tid >> 5;             // 0..7
    int a_m = (tid & 31) << 2;      // 0..124
    int b_n = tid >> 1;             // 0..127
    int b_k = (tid & 1) << 2;       // 0 or 4

    const float* Ap = X  + (size_t)a_k * TT + m0 + a_m;
    const float* Bp = Wp + (size_t)(n0 + b_n) * CC + b_k;

    for (int kt = 0; kt < CC / 8; ++kt) {
        float4 av  = *(const float4*)Ap;
        float4 bv4 = *(const float4*)Bp;
        *(float4*)&As[a_k][a_m] = av;
        Bs[b_k + 0][b_n] = bv4.x;
        Bs[b_k + 1][b_n] = bv4.y;
        Bs[b_k + 2][b_n] = bv4.z;
        Bs[b_k + 3][b_n] = bv4.w;
        __syncthreads();
#pragma unroll
        for (int k = 0; k < 8; ++k) {
            float4 a0  = *(const float4*)&As[k][ty * 8];
            float4 a1  = *(const float4*)&As[k][ty * 8 + 4];
            float4 bb0 = *(const float4*)&Bs[k][tx * 8];
            float4 bb1 = *(const float4*)&Bs[k][tx * 8 + 4];
            float ar[8] = {a0.x, a0.y, a0.z, a0.w, a1.x, a1.y, a1.z, a1.w};
            float br[8] = {bb0.x, bb0.y, bb0.z, bb0.w, bb1.x, bb1.y, bb1.z, bb1.w};
#pragma unroll
            for (int i = 0; i < 8; ++i)
#pragma unroll
                for (int j = 0; j < 8; ++j)
                    acc[i][j] += ar[i] * br[j];
        }
        __syncthreads();
        Ap += 8 * TT;
        Bp += 8;
    }

    float bias[8];
#pragma unroll
    for (int j = 0; j < 8; ++j) bias[j] = bp[n0 + tx * 8 + j];
#pragma unroll
    for (int i = 0; i < 8; ++i) {
        float* cr = Cout + (size_t)(m0 + ty * 8 + i) * OUT_C + n0 + tx * 8;
        float4 o0 = make_float4(acc[i][0] + bias[0], acc[i][1] + bias[1],
                                acc[i][2] + bias[2], acc[i][3] + bias[3]);
        float4 o1 = make_float4(acc[i][4] + bias[4], acc[i][5] + bias[5],
                                acc[i][6] + bias[6], acc[i][7] + bias[7]);
        *(float4*)cr       = o0;
        *(float4*)(cr + 4) = o1;
    }
}

// ---------------- flash attention -------------------------------------------
// One block = (dir, b, h, 64-query tile). 256 threads as 16x16; each thread
// owns a 4x4 micro-tile of S (rows=q, cols=k) and of O (rows=q, cols=d).
// Q,K staged d-major in shared so the S loop is pure LDS.128 + FFMA; P staged
// j-major for the same reason in the PV loop. Softmax running (m,l) is kept
// redundantly in registers by all 16 threads of a row group (identical after
// the shfl reductions), so no shared-stat races.
__global__ __launch_bounds__(256) void attn_kernel()
{
    extern __shared__ float smdyn[];
    float* Qt = smdyn;               // [64 d][68] : Qt[d*68 + q]
    float* Kt = smdyn + 64 * 68;     // [64 d][68] : Kt[d*68 + j]
    float* Vs = smdyn + 2 * 64 * 68; // [64 j][68] : Vs[j*68 + d]
    float* Pt = smdyn + 3 * 64 * 68; // [64 j][68] : Pt[j*68 + i]

    int qt = blockIdx.x, h = blockIdx.y, z = blockIdx.z;
    int dir = z >> 3, b = z & 7;
    int skv = 1 - dir;
    const float* Qp = &g_qkv[dir][0][b][0][h * HD];
    const float* Kp = &g_qkv[skv][1][b][0][h * HD];
    const float* Vp = &g_qkv[skv][2][b][0][h * HD];
    float*       Op = &g_att[dir][b][0][h * HD];

    int tid = threadIdx.x;
    int tx = tid & 15, ty = tid >> 4;
    int q0 = qt * 64;

    // load Q tile transposed (d-major)
    {
        int row = tid >> 4;
        int d4  = (tid & 15) << 2;
#pragma unroll
        for (int r = 0; r < 4; ++r) {
            int q = row + r * 16;
            float4 v = *(const float4*)&Qp[(size_t)(q0 + q) * OUT_C + d4];
            Qt[(d4 + 0) * 68 + q] = v.x;
            Qt[(d4 + 1) * 68 + q] = v.y;
            Qt[(d4 + 2) * 68 + q] = v.z;
            Qt[(d4 + 3) * 68 + q] = v.w;
        }
    }

    float m_i[4], l_i[4], o_acc[4][4];
#pragma unroll
    for (int i = 0; i < 4; ++i) {
        m_i[i] = -1e30f; l_i[i] = 0.f;
#pragma unroll
        for (int j = 0; j < 4; ++j) o_acc[i][j] = 0.f;
    }

    for (int kt2 = 0; kt2 < 16; ++kt2) {
        __syncthreads();   // prev PV done; also covers Q staging on iter 0
        {
            int row = tid >> 4;
            int d4  = (tid & 15) << 2;
#pragma unroll
            for (int r = 0; r < 4; ++r) {
                int j = row + r * 16;
                size_t g = (size_t)(kt2 * 64 + j) * OUT_C + d4;
                float4 kv = *(const float4*)&Kp[g];
                Kt[(d4 + 0) * 68 + j] = kv.x;
                Kt[(d4 + 1) * 68 + j] = kv.y;
                Kt[(d4 + 2) * 68 + j] = kv.z;
                Kt[(d4 + 3) * 68 + j] = kv.w;
                float4 vv = *(const float4*)&Vp[g];
                *(float4*)&Vs[j * 68 + d4] = vv;
            }
        }
        __syncthreads();

        // S = Q @ K^T (micro 4x4, loop over d)
        float s[4][4] = {};
#pragma unroll 8
        for (int d = 0; d < 64; ++d) {
            float4 qa = *(const float4*)&Qt[d * 68 + ty * 4];
            float4 kb = *(const float4*)&Kt[d * 68 + tx * 4];
            float qr[4] = {qa.x, qa.y, qa.z, qa.w};
            float kr[4] = {kb.x, kb.y, kb.z, kb.w};
#pragma unroll
            for (int i = 0; i < 4; ++i)
#pragma unroll
                for (int j = 0; j < 4; ++j)
                    s[i][j] += qr[i] * kr[j];
        }
#pragma unroll
        for (int i = 0; i < 4; ++i)
#pragma unroll
            for (int j = 0; j < 4; ++j)
                s[i][j] *= 0.03125f;     // 1/sqrt(EMBED_DIM=1024)

        // online softmax
        float rm[4], rs[4], alpha[4];
#pragma unroll
        for (int i = 0; i < 4; ++i) {
            rm[i] = fmaxf(fmaxf(s[i][0], s[i][1]), fmaxf(s[i][2], s[i][3]));
#pragma unroll
            for (int off = 1; off < 16; off <<= 1)
                rm[i] = fmaxf(rm[i], __shfl_xor_sync(0xffffffffu, rm[i], off));
            float mn = fmaxf(m_i[i], rm[i]);
            alpha[i] = __expf(m_i[i] - mn);
            m_i[i] = mn;
            rs[i] = 0.f;
#pragma unroll
            for (int j = 0; j < 4; ++j) {
                float p = __expf(s[i][j] - m_i[i]);
                s[i][j] = p;
                rs[i] += p;
            }
#pragma unroll
            for (int off = 1; off < 16; off <<= 1)
                rs[i] += __shfl_xor_sync(0xffffffffu, rs[i], off);
            l_i[i] = l_i[i] * alpha[i] + rs[i];
#pragma unroll
            for (int d = 0; d < 4; ++d) o_acc[i][d] *= alpha[i];
        }

        // stage P transposed (j-major)
#pragma unroll
        for (int i = 0; i < 4; ++i)
#pragma unroll
            for (int j = 0; j < 4; ++j)
                Pt[(tx * 4 + j) * 68 + ty * 4 + i] = s[i][j];
        __syncthreads();

        // O += P @ V
#pragma unroll 8
        for (int j = 0; j < 64; ++j) {
            float4 pa = *(const float4*)&Pt[j * 68 + ty * 4];
            float4 vb = *(const float4*)&Vs[j * 68 + tx * 4];
            float pr[4] = {pa.x, pa.y, pa.z, pa.w};
            float vr[4] = {vb.x, vb.y, vb.z, vb.w};
#pragma unroll
            for (int i = 0; i < 4; ++i)
#pragma unroll
                for (int d = 0; d < 4; ++d)
                    o_acc[i][d] += pr[i] * vr[d];
        }
    }

#pragma unroll
    for (int i = 0; i < 4; ++i) {
        float inv = 1.f / l_i[i];
        float4 o = make_float4(o_acc[i][0] * inv, o_acc[i][1] * inv,
                               o_acc[i][2] * inv, o_acc[i][3] * inv);
        *(float4*)&Op[(size_t)(q0 + ty * 4 + i) * OUT_C + tx * 4] = o;
    }
}

// ---------------- mix + LayerNorm -------------------------------------------
__global__ __launch_bounds__(256) void mixln_kernel(
    const float* __restrict__ wmix, const float* __restrict__ ln_g,
    const float* __restrict__ ln_b)
{
    int row = blockIdx.x;                       // 0..8191 (b*T + t)
    const float* a0 = &g_att[0][0][0][0] + (size_t)row * OUT_C;  // attended_vit
    const float* a1 = &g_att[1][0][0][0] + (size_t)row * OUT_C;  // attended_cnn
    float wm = *wmix;
    int tid = threadIdx.x;

    float v[8];
    float sum = 0.f, sq = 0.f;
#pragma unroll
    for (int k = 0; k < 8; ++k) {
        int c = tid + k * 256;
        float x = a1[c] * wm + a0[c] * (1.f - wm);
        v[k] = x; sum += x; sq += x * x;
    }
#pragma unroll
    for (int off = 16; off; off >>= 1) {
        sum += __shfl_xor_sync(0xffffffffu, sum, off);
        sq  += __shfl_xor_sync(0xffffffffu, sq,  off);
    }
    __shared__ float red[2][8];
    if ((tid & 31) == 0) { red[0][tid >> 5] = sum; red[1][tid >> 5] = sq; }
    __syncthreads();
    float ts = 0.f, t2 = 0.f;
#pragma unroll
    for (int w2 = 0; w2 < 8; ++w2) { ts += red[0][w2]; t2 += red[1][w2]; }
    float mu   = ts * (1.f / 2048.f);
    float var  = t2 * (1.f / 2048.f) - mu * mu;
    float rstd = rsqrtf(var + 1e-5f);
#pragma unroll
    for (int k = 0; k < 8; ++k) {
        int c = tid + k * 256;
        g_r[row][c] = (v[k] - mu) * rstd * ln_g[c] + ln_b[c];
    }
}

// ---------------- FC GEMM: g_fc = g_r @ Wfc^T + bfc -------------------------
__global__ __launch_bounds__(256, 2) void fc_gemm(
    const float* __restrict__ Wfc, const float* __restrict__ bfc)
{
    const float* A = &g_r[0][0];    // [8192][2048] row-major

    __shared__ float As[8][132];
    __shared__ float Bs[8][132];

    int tid = threadIdx.x;
    int tx = tid & 15, ty = tid >> 4;
    int m0 = blockIdx.y * 128;
    int n0 = blockIdx.x * 128;

    float acc[8][8] = {};

    int r_l = tid >> 1;             // 0..127
    int k_l = (tid & 1) << 2;       // 0 or 4

    const float* Ap = A   + (size_t)(m0 + r_l) * OUT_C + k_l;
    const float* Bp = Wfc + (size_t)(n0 + r_l) * OUT_C + k_l;

    for (int kt = 0; kt < OUT_C / 8; ++kt) {
        float4 av = *(const float4*)Ap;
        float4 bv = *(const float4*)Bp;
        As[k_l + 0][r_l] = av.x; As[k_l + 1][r_l] = av.y;
        As[k_l + 2][r_l] = av.z; As[k_l + 3][r_l] = av.w;
        Bs[k_l + 0][r_l] = bv.x; Bs[k_l + 1][r_l] = bv.y;
        Bs[k_l + 2][r_l] = bv.z; Bs[k_l + 3][r_l] = bv.w;
        __syncthreads();
#pragma unroll
        for (int k = 0; k < 8; ++k) {
            float4 a0  = *(const float4*)&As[k][ty * 8];
            float4 a1  = *(const float4*)&As[k][ty * 8 + 4];
            float4 bb0 = *(const float4*)&Bs[k][tx * 8];
            float4 bb1 = *(const float4*)&Bs[k][tx * 8 + 4];
            float ar[8] = {a0.x, a0.y, a0.z, a0.w, a1.x, a1.y, a1.z, a1.w};
            float br[8] = {bb0.x, bb0.y, bb0.z, bb0.w, bb1.x, bb1.y, bb1.z, bb1.w};
#pragma unroll
            for (int i = 0; i < 8; ++i)
#pragma unroll
                for (int j = 0; j < 8; ++j)
                    acc[i][j] += ar[i] * br[j];
        }
        __syncthreads();
        Ap += 8;
        Bp += 8;
    }

    float bias[8];
#pragma unroll
    for (int j = 0; j < 8; ++j) bias[j] = bfc[n0 + tx * 8 + j];
#pragma unroll
    for (int i = 0; i < 8; ++i) {
        float* cr = &g_fc[m0 + ty * 8 + i][n0 + tx * 8];
        float4 o0 = make_float4(acc[i][0] + bias[0], acc[i][1] + bias[1],
                                acc[i][2] + bias[2], acc[i][3] + bias[3]);
        float4 o1 = make_float4(acc[i][4] + bias[4], acc[i][5] + bias[5],
                                acc[i][6] + bias[6], acc[i][7] + bias[7]);
        *(float4*)cr       = o0;
        *(float4*)(cr + 4) = o1;
    }
}

// ---------------- final transpose: out[b][o][t] = g_fc[b*T + t][o] ----------
__global__ void transpose_out(float* __restrict__ out)
{
    __shared__ float tile[32][33];
    int b  = blockIdx.z;
    int o0 = blockIdx.x * 32, t0 = blockIdx.y * 32;
    int tx2 = threadIdx.x, ty2 = threadIdx.y;   // (32, 8)
#pragma unroll
    for (int r = 0; r < 4; ++r)
        tile[ty2 + r * 8][tx2] = g_fc[(size_t)b * TT + t0 + ty2 + r * 8][o0 + tx2];
    __syncthreads();
#pragma unroll
    for (int r = 0; r < 4; ++r)
        out[((size_t)b * OUT_C + o0 + ty2 + r * 8) * TT + t0 + tx2] =
            tile[tx2][ty2 + r * 8];
}

// ---------------- launch ----------------------------------------------------
extern "C" void kernel_launch(void* const* d_in, const int* in_sizes, int n_in,
                              void* d_out, int out_size)
{
    const float* x_cnn = (const float*)d_in[0];
    const float* x_vit = (const float*)d_in[1];
    const float* Wq    = (const float*)d_in[2];
    const float* bq    = (const float*)d_in[3];
    const float* Wk    = (const float*)d_in[4];
    const float* bk    = (const float*)d_in[5];
    const float* Wv    = (const float*)d_in[6];
    const float* bv    = (const float*)d_in[7];
    const float* w_mix = (const float*)d_in[8];
    const float* ln_g  = (const float*)d_in[9];
    const float* ln_b  = (const float*)d_in[10];
    const float* Wfc   = (const float*)d_in[11];
    const float* bfc   = (const float*)d_in[12];
    float* out = (float*)d_out;

    const int ATT_SMEM = 4 * 64 * 68 * (int)sizeof(float);  // 69632 B
    cudaFuncSetAttribute(attn_kernel,
                         cudaFuncAttributeMaxDynamicSharedMemorySize, ATT_SMEM);

    // 6 projection GEMMs (48 sub-problems in grid.z)
    proj_gemm<<<dim3(16, 8, 48), 256>>>(x_cnn, x_vit, Wq, bq, Wk, bk, Wv, bv);
    // dual-direction flash attention (16 q-tiles x 32 heads x 16 dir*batch)
    attn_kernel<<<dim3(16, 32, 16), 256, ATT_SMEM>>>();
    // mix + LayerNorm
    mixln_kernel<<<NB * TT, 256>>>(w_mix, ln_g, ln_b);
    // FC GEMM
    fc_gemm<<<dim3(16, 64), 256>>>(Wfc, bfc);
    // final [b][t][o] -> [b][o][t]
    transpose_out<<<dim3(64, 32, 8), dim3(32, 8)>>>(out);
}

// round 5
// speedup vs baseline: 1.4621x; 1.4621x over previous
#include <cuda_runtime.h>

#define CC    1024   // in channels (= K for projections)
#define TT    1024   // tokens = H*W
#define OUT_C 2048
#define NB    8
#define NH    32
#define HD    64

// ---------------- scratch (static device globals; no runtime allocation) ----
__device__ float g_qkv[2][3][NB][TT][OUT_C];
__device__ float g_att[2][NB][TT][OUT_C];
__device__ float g_r[NB * TT][OUT_C];
__device__ float g_fc[NB * TT][OUT_C];

// ---------------- tf32 helpers ----------------------------------------------
__device__ __forceinline__ unsigned f2tf(float x) {
    unsigned r;
    asm("cvt.rna.tf32.f32 %0, %1;" : "=r"(r) : "f"(x));
    return r;
}

__device__ __forceinline__ void mma8(float* d, const unsigned* a, const unsigned* b) {
    asm volatile(
        "mma.sync.aligned.m16n8k8.row.col.f32.tf32.tf32.f32 "
        "{%0,%1,%2,%3}, {%4,%5,%6,%7}, {%8,%9}, {%0,%1,%2,%3};"
        : "+f"(d[0]), "+f"(d[1]), "+f"(d[2]), "+f"(d[3])
        : "r"(a[0]), "r"(a[1]), "r"(a[2]), "r"(a[3]), "r"(b[0]), "r"(b[1]));
}

// ---------------- projection GEMM (tf32 tensor cores) ------------------------
// Y[t][o] = sum_c X[c][t] * W[o][c] + b[o].  X is [C][T] (k-major): A tile
// loads are coalesced along t and land directly in k-major shared.
__global__ __launch_bounds__(256, 2) void proj_gemm_tc(
    const float* __restrict__ xc, const float* __restrict__ xv,
    const float* __restrict__ Wq, const float* __restrict__ bq,
    const float* __restrict__ Wk, const float* __restrict__ bk,
    const float* __restrict__ Wv, const float* __restrict__ bv)
{
    int z = blockIdx.z;
    int w  = z % 3;
    int sb = z / 3;
    int s = sb >> 3, b = sb & 7;
    const float* X  = (s == 0 ? xc : xv) + (size_t)b * CC * TT;      // [C][T]
    const float* Wp = (w == 0) ? Wq : ((w == 1) ? Wk : Wv);          // [OUT][C]
    const float* bp = (w == 0) ? bq : ((w == 1) ? bk : bv);
    float* Cout = &g_qkv[s][w][b][0][0];

    __shared__ unsigned As[16][136];   // [k][m], stride 136 -> conflict-free frag loads
    __shared__ unsigned Bs[16][136];   // [k][n]

    int tid  = threadIdx.x;
    int warp = tid >> 5, lane = tid & 31;
    int g = lane >> 2, t = lane & 3;
    int wm = warp >> 2;        // 0..1  (64-row warp tile)
    int wn = warp & 3;         // 0..3  (32-col warp tile)
    int m0 = blockIdx.y * 128;
    int n0 = blockIdx.x * 128;

    // staging maps
    int ak_s = tid >> 4;               // 0..15 : k row of A
    int am_s = (tid & 15) << 3;        // 0..120: 8 m floats
    int bn_s = tid & 127;              // 0..127: n row of B
    int bk_s = (tid >> 7) << 3;        // 0 or 8: 8 k floats

    float acc[4][4][4] = {};

    for (int kt = 0; kt < CC / 16; ++kt) {
        int kbase = kt * 16;
        // global loads (issue early, consumed after sync)
        const float* ap = X + (size_t)(kbase + ak_s) * TT + m0 + am_s;
        float4 a0v = *(const float4*)ap;
        float4 a1v = *(const float4*)(ap + 4);
        const float* wp2 = Wp + (size_t)(n0 + bn_s) * CC + kbase + bk_s;
        float4 w0 = *(const float4*)wp2;
        float4 w1 = *(const float4*)(wp2 + 4);

        __syncthreads();   // previous tile fully consumed
        {
            uint4 p0 = make_uint4(f2tf(a0v.x), f2tf(a0v.y), f2tf(a0v.z), f2tf(a0v.w));
            uint4 p1 = make_uint4(f2tf(a1v.x), f2tf(a1v.y), f2tf(a1v.z), f2tf(a1v.w));
            *(uint4*)&As[ak_s][am_s]     = p0;
            *(uint4*)&As[ak_s][am_s + 4] = p1;
            Bs[bk_s + 0][bn_s] = f2tf(w0.x); Bs[bk_s + 1][bn_s] = f2tf(w0.y);
            Bs[bk_s + 2][bn_s] = f2tf(w0.z); Bs[bk_s + 3][bn_s] = f2tf(w0.w);
            Bs[bk_s + 4][bn_s] = f2tf(w1.x); Bs[bk_s + 5][bn_s] = f2tf(w1.y);
            Bs[bk_s + 6][bn_s] = f2tf(w1.z); Bs[bk_s + 7][bn_s] = f2tf(w1.w);
        }
        __syncthreads();

#pragma unroll
        for (int kk = 0; kk < 2; ++kk) {
            int k0 = kk * 8;
            unsigned af[4][4], bf[4][2];
#pragma unroll
            for (int mi = 0; mi < 4; ++mi) {
                int m = wm * 64 + mi * 16 + g;
                af[mi][0] = As[k0 + t][m];
                af[mi][1] = As[k0 + t][m + 8];
                af[mi][2] = As[k0 + t + 4][m];
                af[mi][3] = As[k0 + t + 4][m + 8];
            }
#pragma unroll
            for (int ni = 0; ni < 4; ++ni) {
                int n = wn * 32 + ni * 8 + g;
                bf[ni][0] = Bs[k0 + t][n];
                bf[ni][1] = Bs[k0 + t + 4][n];
            }
#pragma unroll
            for (int mi = 0; mi < 4; ++mi)
#pragma unroll
                for (int ni = 0; ni < 4; ++ni)
                    mma8(acc[mi][ni], af[mi], bf[ni]);
        }
    }

#pragma unroll
    for (int mi = 0; mi < 4; ++mi) {
#pragma unroll
        for (int ni = 0; ni < 4; ++ni) {
            int row = m0 + wm * 64 + mi * 16 + g;
            int col = n0 + wn * 32 + ni * 8 + 2 * t;
            float b0 = bp[col], b1 = bp[col + 1];
            float* c0 = Cout + (size_t)row * OUT_C + col;
            float* c1 = Cout + (size_t)(row + 8) * OUT_C + col;
            *(float2*)c0 = make_float2(acc[mi][ni][0] + b0, acc[mi][ni][1] + b1);
            *(float2*)c1 = make_float2(acc[mi][ni][2] + b0, acc[mi][ni][3] + b1);
        }
    }
}

// ---------------- FC GEMM (tf32): g_fc = g_r @ Wfc^T + bfc -------------------
__global__ __launch_bounds__(256, 2) void fc_gemm_tc(
    const float* __restrict__ Wfc, const float* __restrict__ bfc)
{
    const float* A = &g_r[0][0];    // [8192][2048] row-major (m-major)

    __shared__ unsigned As[16][136];
    __shared__ unsigned Bs[16][136];

    int tid  = threadIdx.x;
    int warp = tid >> 5, lane = tid & 31;
    int g = lane >> 2, t = lane & 3;
    int wm = warp >> 2, wn = warp & 3;
    int m0 = blockIdx.y * 128;
    int n0 = blockIdx.x * 128;

    int rr = tid & 127;              // row (m for A, n for B)
    int rk = (tid >> 7) << 3;        // 0 or 8

    float acc[4][4][4] = {};

    for (int kt = 0; kt < OUT_C / 16; ++kt) {
        int kbase = kt * 16;
        const float* ap  = A   + (size_t)(m0 + rr) * OUT_C + kbase + rk;
        const float* wp2 = Wfc + (size_t)(n0 + rr) * OUT_C + kbase + rk;
        float4 a0v = *(const float4*)ap;
        float4 a1v = *(const float4*)(ap + 4);
        float4 w0 = *(const float4*)wp2;
        float4 w1 = *(const float4*)(wp2 + 4);

        __syncthreads();
        As[rk + 0][rr] = f2tf(a0v.x); As[rk + 1][rr] = f2tf(a0v.y);
        As[rk + 2][rr] = f2tf(a0v.z); As[rk + 3][rr] = f2tf(a0v.w);
        As[rk + 4][rr] = f2tf(a1v.x); As[rk + 5][rr] = f2tf(a1v.y);
        As[rk + 6][rr] = f2tf(a1v.z); As[rk + 7][rr] = f2tf(a1v.w);
        Bs[rk + 0][rr] = f2tf(w0.x);  Bs[rk + 1][rr] = f2tf(w0.y);
        Bs[rk + 2][rr] = f2tf(w0.z);  Bs[rk + 3][rr] = f2tf(w0.w);
        Bs[rk + 4][rr] = f2tf(w1.x);  Bs[rk + 5][rr] = f2tf(w1.y);
        Bs[rk + 6][rr] = f2tf(w1.z);  Bs[rk + 7][rr] = f2tf(w1.w);
        __syncthreads();

#pragma unroll
        for (int kk = 0; kk < 2; ++kk) {
            int k0 = kk * 8;
            unsigned af[4][4], bf[4][2];
#pragma unroll
            for (int mi = 0; mi < 4; ++mi) {
                int m = wm * 64 + mi * 16 + g;
                af[mi][0] = As[k0 + t][m];
                af[mi][1] = As[k0 + t][m + 8];
                af[mi][2] = As[k0 + t + 4][m];
                af[mi][3] = As[k0 + t + 4][m + 8];
            }
#pragma unroll
            for (int ni = 0; ni < 4; ++ni) {
                int n = wn * 32 + ni * 8 + g;
                bf[ni][0] = Bs[k0 + t][n];
                bf[ni][1] = Bs[k0 + t + 4][n];
            }
#pragma unroll
            for (int mi = 0; mi < 4; ++mi)
#pragma unroll
                for (int ni = 0; ni < 4; ++ni)
                    mma8(acc[mi][ni], af[mi], bf[ni]);
        }
    }

#pragma unroll
    for (int mi = 0; mi < 4; ++mi) {
#pragma unroll
        for (int ni = 0; ni < 4; ++ni) {
            int row = m0 + wm * 64 + mi * 16 + g;
            int col = n0 + wn * 32 + ni * 8 + 2 * t;
            float b0 = bfc[col], b1 = bfc[col + 1];
            *(float2*)&g_fc[row][col] =
                make_float2(acc[mi][ni][0] + b0, acc[mi][ni][1] + b1);
            *(float2*)&g_fc[row + 8][col] =
                make_float2(acc[mi][ni][2] + b0, acc[mi][ni][3] + b1);
        }
    }
}

// ---------------- flash attention (fp32, unchanged from R1) ------------------
__global__ __launch_bounds__(256) void attn_kernel()
{
    extern __shared__ float smdyn[];
    float* Qt = smdyn;               // [64 d][68]
    float* Kt = smdyn + 64 * 68;     // [64 d][68]
    float* Vs = smdyn + 2 * 64 * 68; // [64 j][68]
    float* Pt = smdyn + 3 * 64 * 68; // [64 j][68]

    int qt = blockIdx.x, h = blockIdx.y, z = blockIdx.z;
    int dir = z >> 3, b = z & 7;
    int skv = 1 - dir;
    const float* Qp = &g_qkv[dir][0][b][0][h * HD];
    const float* Kp = &g_qkv[skv][1][b][0][h * HD];
    const float* Vp = &g_qkv[skv][2][b][0][h * HD];
    float*       Op = &g_att[dir][b][0][h * HD];

    int tid = threadIdx.x;
    int tx = tid & 15, ty = tid >> 4;
    int q0 = qt * 64;

    {
        int row = tid >> 4;
        int d4  = (tid & 15) << 2;
#pragma unroll
        for (int r = 0; r < 4; ++r) {
            int q = row + r * 16;
            float4 v = *(const float4*)&Qp[(size_t)(q0 + q) * OUT_C + d4];
            Qt[(d4 + 0) * 68 + q] = v.x;
            Qt[(d4 + 1) * 68 + q] = v.y;
            Qt[(d4 + 2) * 68 + q] = v.z;
            Qt[(d4 + 3) * 68 + q] = v.w;
        }
    }

    float m_i[4], l_i[4], o_acc[4][4];
#pragma unroll
    for (int i = 0; i < 4; ++i) {
        m_i[i] = -1e30f; l_i[i] = 0.f;
#pragma unroll
        for (int j = 0; j < 4; ++j) o_acc[i][j] = 0.f;
    }

    for (int kt2 = 0; kt2 < 16; ++kt2) {
        __syncthreads();
        {
            int row = tid >> 4;
            int d4  = (tid & 15) << 2;
#pragma unroll
            for (int r = 0; r < 4; ++r) {
                int j = row + r * 16;
                size_t gg = (size_t)(kt2 * 64 + j) * OUT_C + d4;
                float4 kv = *(const float4*)&Kp[gg];
                Kt[(d4 + 0) * 68 + j] = kv.x;
                Kt[(d4 + 1) * 68 + j] = kv.y;
                Kt[(d4 + 2) * 68 + j] = kv.z;
                Kt[(d4 + 3) * 68 + j] = kv.w;
                float4 vv = *(const float4*)&Vp[gg];
                *(float4*)&Vs[j * 68 + d4] = vv;
            }
        }
        __syncthreads();

        float s[4][4] = {};
#pragma unroll 8
        for (int d = 0; d < 64; ++d) {
            float4 qa = *(const float4*)&Qt[d * 68 + ty * 4];
            float4 kb = *(const float4*)&Kt[d * 68 + tx * 4];
            float qr[4] = {qa.x, qa.y, qa.z, qa.w};
            float kr[4] = {kb.x, kb.y, kb.z, kb.w};
#pragma unroll
            for (int i = 0; i < 4; ++i)
#pragma unroll
                for (int j = 0; j < 4; ++j)
                    s[i][j] += qr[i] * kr[j];
        }
#pragma unroll
        for (int i = 0; i < 4; ++i)
#pragma unroll
            for (int j = 0; j < 4; ++j)
                s[i][j] *= 0.03125f;

        float rm[4], rs[4], alpha[4];
#pragma unroll
        for (int i = 0; i < 4; ++i) {
            rm[i] = fmaxf(fmaxf(s[i][0], s[i][1]), fmaxf(s[i][2], s[i][3]));
#pragma unroll
            for (int off = 1; off < 16; off <<= 1)
                rm[i] = fmaxf(rm[i], __shfl_xor_sync(0xffffffffu, rm[i], off));
            float mn = fmaxf(m_i[i], rm[i]);
            alpha[i] = __expf(m_i[i] - mn);
            m_i[i] = mn;
            rs[i] = 0.f;
#pragma unroll
            for (int j = 0; j < 4; ++j) {
                float p = __expf(s[i][j] - m_i[i]);
                s[i][j] = p;
                rs[i] += p;
            }
#pragma unroll
            for (int off = 1; off < 16; off <<= 1)
                rs[i] += __shfl_xor_sync(0xffffffffu, rs[i], off);
            l_i[i] = l_i[i] * alpha[i] + rs[i];
#pragma unroll
            for (int d = 0; d < 4; ++d) o_acc[i][d] *= alpha[i];
        }

#pragma unroll
        for (int i = 0; i < 4; ++i)
#pragma unroll
            for (int j = 0; j < 4; ++j)
                Pt[(tx * 4 + j) * 68 + ty * 4 + i] = s[i][j];
        __syncthreads();

#pragma unroll 8
        for (int j = 0; j < 64; ++j) {
            float4 pa = *(const float4*)&Pt[j * 68 + ty * 4];
            float4 vb = *(const float4*)&Vs[j * 68 + tx * 4];
            float pr[4] = {pa.x, pa.y, pa.z, pa.w};
            float vr[4] = {vb.x, vb.y, vb.z, vb.w};
#pragma unroll
            for (int i = 0; i < 4; ++i)
#pragma unroll
                for (int d = 0; d < 4; ++d)
                    o_acc[i][d] += pr[i] * vr[d];
        }
    }

#pragma unroll
    for (int i = 0; i < 4; ++i) {
        float inv = 1.f / l_i[i];
        float4 o = make_float4(o_acc[i][0] * inv, o_acc[i][1] * inv,
                               o_acc[i][2] * inv, o_acc[i][3] * inv);
        *(float4*)&Op[(size_t)(q0 + ty * 4 + i) * OUT_C + tx * 4] = o;
    }
}

// ---------------- mix + LayerNorm -------------------------------------------
__global__ __launch_bounds__(256) void mixln_kernel(
    const float* __restrict__ wmix, const float* __restrict__ ln_g,
    const float* __restrict__ ln_b)
{
    int row = blockIdx.x;
    const float* a0 = &g_att[0][0][0][0] + (size_t)row * OUT_C;
    const float* a1 = &g_att[1][0][0][0] + (size_t)row * OUT_C;
    float wm = *wmix;
    int tid = threadIdx.x;

    float v[8];
    float sum = 0.f, sq = 0.f;
#pragma unroll
    for (int k = 0; k < 8; ++k) {
        int c = tid + k * 256;
        float x = a1[c] * wm + a0[c] * (1.f - wm);
        v[k] = x; sum += x; sq += x * x;
    }
#pragma unroll
    for (int off = 16; off; off >>= 1) {
        sum += __shfl_xor_sync(0xffffffffu, sum, off);
        sq  += __shfl_xor_sync(0xffffffffu, sq,  off);
    }
    __shared__ float red[2][8];
    if ((tid & 31) == 0) { red[0][tid >> 5] = sum; red[1][tid >> 5] = sq; }
    __syncthreads();
    float ts = 0.f, t2 = 0.f;
#pragma unroll
    for (int w2 = 0; w2 < 8; ++w2) { ts += red[0][w2]; t2 += red[1][w2]; }
    float mu   = ts * (1.f / 2048.f);
    float var  = t2 * (1.f / 2048.f) - mu * mu;
    float rstd = rsqrtf(var + 1e-5f);
#pragma unroll
    for (int k = 0; k < 8; ++k) {
        int c = tid + k * 256;
        g_r[row][c] = (v[k] - mu) * rstd * ln_g[c] + ln_b[c];
    }
}

// ---------------- final transpose: out[b][o][t] = g_fc[b*T + t][o] ----------
__global__ void transpose_out(float* __restrict__ out)
{
    __shared__ float tile[32][33];
    int b  = blockIdx.z;
    int o0 = blockIdx.x * 32, t0 = blockIdx.y * 32;
    int tx2 = threadIdx.x, ty2 = threadIdx.y;
#pragma unroll
    for (int r = 0; r < 4; ++r)
        tile[ty2 + r * 8][tx2] = g_fc[(size_t)b * TT + t0 + ty2 + r * 8][o0 + tx2];
    __syncthreads();
#pragma unroll
    for (int r = 0; r < 4; ++r)
        out[((size_t)b * OUT_C + o0 + ty2 + r * 8) * TT + t0 + tx2] =
            tile[tx2][ty2 + r * 8];
}

// ---------------- launch ----------------------------------------------------
extern "C" void kernel_launch(void* const* d_in, const int* in_sizes, int n_in,
                              void* d_out, int out_size)
{
    const float* x_cnn = (const float*)d_in[0];
    const float* x_vit = (const float*)d_in[1];
    const float* Wq    = (const float*)d_in[2];
    const float* bq    = (const float*)d_in[3];
    const float* Wk    = (const float*)d_in[4];
    const float* bk    = (const float*)d_in[5];
    const float* Wv    = (const float*)d_in[6];
    const float* bv    = (const float*)d_in[7];
    const float* w_mix = (const float*)d_in[8];
    const float* ln_g  = (const float*)d_in[9];
    const float* ln_b  = (const float*)d_in[10];
    const float* Wfc   = (const float*)d_in[11];
    const float* bfc   = (const float*)d_in[12];
    float* out = (float*)d_out;

    const int ATT_SMEM = 4 * 64 * 68 * (int)sizeof(float);  // 69632 B
    cudaFuncSetAttribute(attn_kernel,
                         cudaFuncAttributeMaxDynamicSharedMemorySize, ATT_SMEM);

    proj_gemm_tc<<<dim3(16, 8, 48), 256>>>(x_cnn, x_vit, Wq, bq, Wk, bk, Wv, bv);
    attn_kernel<<<dim3(16, 32, 16), 256, ATT_SMEM>>>();
    mixln_kernel<<<NB * TT, 256>>>(w_mix, ln_g, ln_b);
    fc_gemm_tc<<<dim3(16, 64), 256>>>(Wfc, bfc);
    transpose_out<<<dim3(64, 32, 8), dim3(32, 8)>>>(out);
}

// round 6
// speedup vs baseline: 1.5051x; 1.0294x over previous
#include <cuda_runtime.h>

#define CC    1024
#define TT    1024
#define OUT_C 2048
#define NB    8
#define NH    32
#define HD    64

__device__ float g_qkv[2][3][NB][TT][OUT_C];
__device__ float g_att[2][NB][TT][OUT_C];
__device__ float g_r[NB * TT][OUT_C];
__device__ float g_fc[NB * TT][OUT_C];

__device__ __forceinline__ unsigned f2tf(float x) {
    unsigned r;
    asm("cvt.rna.tf32.f32 %0, %1;" : "=r"(r) : "f"(x));
    return r;
}

__device__ __forceinline__ void mma8(float* d, const unsigned* a, const unsigned* b) {
    asm volatile(
        "mma.sync.aligned.m16n8k8.row.col.f32.tf32.tf32.f32 "
        "{%0,%1,%2,%3}, {%4,%5,%6,%7}, {%8,%9}, {%0,%1,%2,%3};"
        : "+f"(d[0]), "+f"(d[1]), "+f"(d[2]), "+f"(d[3])
        : "r"(a[0]), "r"(a[1]), "r"(a[2]), "r"(a[3]), "r"(b[0]), "r"(b[1]));
}

// ---------------- projection GEMM (tf32, 2-stage double buffer) --------------
__global__ __launch_bounds__(256, 2) void proj_gemm_tc(
    const float* __restrict__ xc, const float* __restrict__ xv,
    const float* __restrict__ Wq, const float* __restrict__ bq,
    const float* __restrict__ Wk, const float* __restrict__ bk,
    const float* __restrict__ Wv, const float* __restrict__ bv)
{
    int z = blockIdx.z;
    int w  = z % 3;
    int sb = z / 3;
    int s = sb >> 3, b = sb & 7;
    const float* X  = (s == 0 ? xc : xv) + (size_t)b * CC * TT;      // [C][T]
    const float* Wp = (w == 0) ? Wq : ((w == 1) ? Wk : Wv);          // [OUT][C]
    const float* bp = (w == 0) ? bq : ((w == 1) ? bk : bv);
    float* Cout = &g_qkv[s][w][b][0][0];

    __shared__ unsigned As[2][16][136];
    __shared__ unsigned Bs[2][16][136];

    int tid  = threadIdx.x;
    int warp = tid >> 5, lane = tid & 31;
    int g = lane >> 2, t = lane & 3;
    int wm = warp >> 2, wn = warp & 3;
    int m0 = blockIdx.y * 128;
    int n0 = blockIdx.x * 128;

    int ak_s = tid >> 4;
    int am_s = (tid & 15) << 3;
    int bn_s = tid & 127;
    int bk_s = (tid >> 7) << 3;

    float acc[4][4][4] = {};
    float4 a0v, a1v, w0v, w1v;

    // preload tile 0
    {
        const float* ap = X + (size_t)ak_s * TT + m0 + am_s;
        a0v = *(const float4*)ap; a1v = *(const float4*)(ap + 4);
        const float* wp2 = Wp + (size_t)(n0 + bn_s) * CC + bk_s;
        w0v = *(const float4*)wp2; w1v = *(const float4*)(wp2 + 4);
    }
    {
        *(uint4*)&As[0][ak_s][am_s] =
            make_uint4(f2tf(a0v.x), f2tf(a0v.y), f2tf(a0v.z), f2tf(a0v.w));
        *(uint4*)&As[0][ak_s][am_s + 4] =
            make_uint4(f2tf(a1v.x), f2tf(a1v.y), f2tf(a1v.z), f2tf(a1v.w));
        Bs[0][bk_s + 0][bn_s] = f2tf(w0v.x); Bs[0][bk_s + 1][bn_s] = f2tf(w0v.y);
        Bs[0][bk_s + 2][bn_s] = f2tf(w0v.z); Bs[0][bk_s + 3][bn_s] = f2tf(w0v.w);
        Bs[0][bk_s + 4][bn_s] = f2tf(w1v.x); Bs[0][bk_s + 5][bn_s] = f2tf(w1v.y);
        Bs[0][bk_s + 6][bn_s] = f2tf(w1v.z); Bs[0][bk_s + 7][bn_s] = f2tf(w1v.w);
    }
    __syncthreads();

    const int NT = CC / 16;
    for (int kt = 0; kt < NT; ++kt) {
        int cur = kt & 1;
        if (kt + 1 < NT) {
            int kb = (kt + 1) * 16;
            const float* ap = X + (size_t)(kb + ak_s) * TT + m0 + am_s;
            a0v = *(const float4*)ap; a1v = *(const float4*)(ap + 4);
            const float* wp2 = Wp + (size_t)(n0 + bn_s) * CC + kb + bk_s;
            w0v = *(const float4*)wp2; w1v = *(const float4*)(wp2 + 4);
        }
#pragma unroll
        for (int kk = 0; kk < 2; ++kk) {
            int k0 = kk * 8;
            unsigned af[4][4], bf[4][2];
#pragma unroll
            for (int mi = 0; mi < 4; ++mi) {
                int m = wm * 64 + mi * 16 + g;
                af[mi][0] = As[cur][k0 + t][m];
                af[mi][1] = As[cur][k0 + t][m + 8];
                af[mi][2] = As[cur][k0 + t + 4][m];
                af[mi][3] = As[cur][k0 + t + 4][m + 8];
            }
#pragma unroll
            for (int ni = 0; ni < 4; ++ni) {
                int n = wn * 32 + ni * 8 + g;
                bf[ni][0] = Bs[cur][k0 + t][n];
                bf[ni][1] = Bs[cur][k0 + t + 4][n];
            }
#pragma unroll
            for (int mi = 0; mi < 4; ++mi)
#pragma unroll
                for (int ni = 0; ni < 4; ++ni)
                    mma8(acc[mi][ni], af[mi], bf[ni]);
        }
        if (kt + 1 < NT) {
            int nb = cur ^ 1;
            *(uint4*)&As[nb][ak_s][am_s] =
                make_uint4(f2tf(a0v.x), f2tf(a0v.y), f2tf(a0v.z), f2tf(a0v.w));
            *(uint4*)&As[nb][ak_s][am_s + 4] =
                make_uint4(f2tf(a1v.x), f2tf(a1v.y), f2tf(a1v.z), f2tf(a1v.w));
            Bs[nb][bk_s + 0][bn_s] = f2tf(w0v.x); Bs[nb][bk_s + 1][bn_s] = f2tf(w0v.y);
            Bs[nb][bk_s + 2][bn_s] = f2tf(w0v.z); Bs[nb][bk_s + 3][bn_s] = f2tf(w0v.w);
            Bs[nb][bk_s + 4][bn_s] = f2tf(w1v.x); Bs[nb][bk_s + 5][bn_s] = f2tf(w1v.y);
            Bs[nb][bk_s + 6][bn_s] = f2tf(w1v.z); Bs[nb][bk_s + 7][bn_s] = f2tf(w1v.w);
        }
        __syncthreads();
    }

#pragma unroll
    for (int mi = 0; mi < 4; ++mi) {
#pragma unroll
        for (int ni = 0; ni < 4; ++ni) {
            int row = m0 + wm * 64 + mi * 16 + g;
            int col = n0 + wn * 32 + ni * 8 + 2 * t;
            float b0 = bp[col], b1 = bp[col + 1];
            float* c0 = Cout + (size_t)row * OUT_C + col;
            float* c1 = Cout + (size_t)(row + 8) * OUT_C + col;
            *(float2*)c0 = make_float2(acc[mi][ni][0] + b0, acc[mi][ni][1] + b1);
            *(float2*)c1 = make_float2(acc[mi][ni][2] + b0, acc[mi][ni][3] + b1);
        }
    }
}

// ---------------- FC GEMM (tf32, 2-stage double buffer) ----------------------
__global__ __launch_bounds__(256, 2) void fc_gemm_tc(
    const float* __restrict__ Wfc, const float* __restrict__ bfc)
{
    const float* A = &g_r[0][0];

    __shared__ unsigned As[2][16][136];
    __shared__ unsigned Bs[2][16][136];

    int tid  = threadIdx.x;
    int warp = tid >> 5, lane = tid & 31;
    int g = lane >> 2, t = lane & 3;
    int wm = warp >> 2, wn = warp & 3;
    int m0 = blockIdx.y * 128;
    int n0 = blockIdx.x * 128;

    int rr = tid & 127;
    int rk = (tid >> 7) << 3;

    float acc[4][4][4] = {};
    float4 a0v, a1v, w0v, w1v;

    {
        const float* ap  = A   + (size_t)(m0 + rr) * OUT_C + rk;
        const float* wp2 = Wfc + (size_t)(n0 + rr) * OUT_C + rk;
        a0v = *(const float4*)ap;  a1v = *(const float4*)(ap + 4);
        w0v = *(const float4*)wp2; w1v = *(const float4*)(wp2 + 4);
    }
    {
        As[0][rk + 0][rr] = f2tf(a0v.x); As[0][rk + 1][rr] = f2tf(a0v.y);
        As[0][rk + 2][rr] = f2tf(a0v.z); As[0][rk + 3][rr] = f2tf(a0v.w);
        As[0][rk + 4][rr] = f2tf(a1v.x); As[0][rk + 5][rr] = f2tf(a1v.y);
        As[0][rk + 6][rr] = f2tf(a1v.z); As[0][rk + 7][rr] = f2tf(a1v.w);
        Bs[0][rk + 0][rr] = f2tf(w0v.x); Bs[0][rk + 1][rr] = f2tf(w0v.y);
        Bs[0][rk + 2][rr] = f2tf(w0v.z); Bs[0][rk + 3][rr] = f2tf(w0v.w);
        Bs[0][rk + 4][rr] = f2tf(w1v.x); Bs[0][rk + 5][rr] = f2tf(w1v.y);
        Bs[0][rk + 6][rr] = f2tf(w1v.z); Bs[0][rk + 7][rr] = f2tf(w1v.w);
    }
    __syncthreads();

    const int NT = OUT_C / 16;
    for (int kt = 0; kt < NT; ++kt) {
        int cur = kt & 1;
        if (kt + 1 < NT) {
            int kb = (kt + 1) * 16;
            const float* ap  = A   + (size_t)(m0 + rr) * OUT_C + kb + rk;
            const float* wp2 = Wfc + (size_t)(n0 + rr) * OUT_C + kb + rk;
            a0v = *(const float4*)ap;  a1v = *(const float4*)(ap + 4);
            w0v = *(const float4*)wp2; w1v = *(const float4*)(wp2 + 4);
        }
#pragma unroll
        for (int kk = 0; kk < 2; ++kk) {
            int k0 = kk * 8;
            unsigned af[4][4], bf[4][2];
#pragma unroll
            for (int mi = 0; mi < 4; ++mi) {
                int m = wm * 64 + mi * 16 + g;
                af[mi][0] = As[cur][k0 + t][m];
                af[mi][1] = As[cur][k0 + t][m + 8];
                af[mi][2] = As[cur][k0 + t + 4][m];
                af[mi][3] = As[cur][k0 + t + 4][m + 8];
            }
#pragma unroll
            for (int ni = 0; ni < 4; ++ni) {
                int n = wn * 32 + ni * 8 + g;
                bf[ni][0] = Bs[cur][k0 + t][n];
                bf[ni][1] = Bs[cur][k0 + t + 4][n];
            }
#pragma unroll
            for (int mi = 0; mi < 4; ++mi)
#pragma unroll
                for (int ni = 0; ni < 4; ++ni)
                    mma8(acc[mi][ni], af[mi], bf[ni]);
        }
        if (kt + 1 < NT) {
            int nb = cur ^ 1;
            As[nb][rk + 0][rr] = f2tf(a0v.x); As[nb][rk + 1][rr] = f2tf(a0v.y);
            As[nb][rk + 2][rr] = f2tf(a0v.z); As[nb][rk + 3][rr] = f2tf(a0v.w);
            As[nb][rk + 4][rr] = f2tf(a1v.x); As[nb][rk + 5][rr] = f2tf(a1v.y);
            As[nb][rk + 6][rr] = f2tf(a1v.z); As[nb][rk + 7][rr] = f2tf(a1v.w);
            Bs[nb][rk + 0][rr] = f2tf(w0v.x); Bs[nb][rk + 1][rr] = f2tf(w0v.y);
            Bs[nb][rk + 2][rr] = f2tf(w0v.z); Bs[nb][rk + 3][rr] = f2tf(w0v.w);
            Bs[nb][rk + 4][rr] = f2tf(w1v.x); Bs[nb][rk + 5][rr] = f2tf(w1v.y);
            Bs[nb][rk + 6][rr] = f2tf(w1v.z); Bs[nb][rk + 7][rr] = f2tf(w1v.w);
        }
        __syncthreads();
    }

#pragma unroll
    for (int mi = 0; mi < 4; ++mi) {
#pragma unroll
        for (int ni = 0; ni < 4; ++ni) {
            int row = m0 + wm * 64 + mi * 16 + g;
            int col = n0 + wn * 32 + ni * 8 + 2 * t;
            float b0 = bfc[col], b1 = bfc[col + 1];
            *(float2*)&g_fc[row][col] =
                make_float2(acc[mi][ni][0] + b0, acc[mi][ni][1] + b1);
            *(float2*)&g_fc[row + 8][col] =
                make_float2(acc[mi][ni][2] + b0, acc[mi][ni][3] + b1);
        }
    }
}

// ---------------- flash attention on tf32 tensor cores -----------------------
// Block = 128 queries of one (dir, b, h). 8 warps, warp w owns q rows
// [16w, 16w+16). K-tiles of 64 keys. P round-trips through a warp-private
// smem slice (each warp reads/writes only its own 16 q-columns of Ps).
__global__ __launch_bounds__(256, 2) void attn_tc()
{
    extern __shared__ unsigned smext[];
    unsigned (*Ks)[72]  = (unsigned(*)[72]) smext;               // [d=64][key]
    unsigned (*Vs)[72]  = (unsigned(*)[72])(smext + 64 * 72);    // [key=64][d]
    unsigned (*Ps)[136] = (unsigned(*)[136])(smext + 2 * 64 * 72); // [key][q=128]

    int qt = blockIdx.x, h = blockIdx.y, z = blockIdx.z;
    int dir = z >> 3, b = z & 7;
    int skv = 1 - dir;
    const float* Qp = &g_qkv[dir][0][b][0][h * HD];
    const float* Kp = &g_qkv[skv][1][b][0][h * HD];
    const float* Vp = &g_qkv[skv][2][b][0][h * HD];
    float*       Op = &g_att[dir][b][0][h * HD];

    int tid  = threadIdx.x;
    int warp = tid >> 5, lane = tid & 31;
    int g = lane >> 2, t = lane & 3;
    int q0 = qt * 128;

    // stage Q (pre-scaled by 1/32) transposed into Ps[d][q], then load A-frags
    {
        int q  = tid >> 1;
        int dl = (tid & 1) * 4;
#pragma unroll
        for (int p = 0; p < 8; ++p) {
            int d = p * 8 + dl;
            float4 v = *(const float4*)&Qp[(size_t)(q0 + q) * OUT_C + d];
            Ps[d + 0][q] = f2tf(v.x * 0.03125f);
            Ps[d + 1][q] = f2tf(v.y * 0.03125f);
            Ps[d + 2][q] = f2tf(v.z * 0.03125f);
            Ps[d + 3][q] = f2tf(v.w * 0.03125f);
        }
    }
    __syncthreads();
    unsigned qa[8][4];
#pragma unroll
    for (int ks = 0; ks < 8; ++ks) {
        qa[ks][0] = Ps[ks * 8 + t][warp * 16 + g];
        qa[ks][1] = Ps[ks * 8 + t][warp * 16 + g + 8];
        qa[ks][2] = Ps[ks * 8 + t + 4][warp * 16 + g];
        qa[ks][3] = Ps[ks * 8 + t + 4][warp * 16 + g + 8];
    }
    __syncthreads();   // all warps done reading Q from Ps before it is reused

    float m0r = -1e30f, m1r = -1e30f, l0 = 0.f, l1 = 0.f;
    float oa[8][4] = {};

    for (int kt = 0; kt < TT / 64; ++kt) {
        // stage K transposed (Ks[d][key]) and V direct (Vs[key][d])
        {
            int key = tid >> 2;
            int dl  = (tid & 3) * 4;
            const float* kRow = Kp + (size_t)(kt * 64 + key) * OUT_C;
            const float* vRow = Vp + (size_t)(kt * 64 + key) * OUT_C;
#pragma unroll
            for (int p = 0; p < 4; ++p) {
                int d = p * 16 + dl;
                float4 kv = *(const float4*)&kRow[d];
                Ks[d + 0][key] = f2tf(kv.x);
                Ks[d + 1][key] = f2tf(kv.y);
                Ks[d + 2][key] = f2tf(kv.z);
                Ks[d + 3][key] = f2tf(kv.w);
                float4 vv = *(const float4*)&vRow[d];
                Vs[key][d + 0] = f2tf(vv.x);
                Vs[key][d + 1] = f2tf(vv.y);
                Vs[key][d + 2] = f2tf(vv.z);
                Vs[key][d + 3] = f2tf(vv.w);
            }
        }
        __syncthreads();

        // S = Qs @ K^T (already scaled): per warp 16 x 64
        float s[8][4] = {};
#pragma unroll
        for (int ks = 0; ks < 8; ++ks) {
#pragma unroll
            for (int nt = 0; nt < 8; ++nt) {
                unsigned bf[2] = {Ks[ks * 8 + t][nt * 8 + g],
                                  Ks[ks * 8 + t + 4][nt * 8 + g]};
                mma8(s[nt], qa[ks], bf);
            }
        }

        // online softmax (rows g and g+8; stats shared by the 4 lanes per row)
        float tm0 = -1e30f, tm1 = -1e30f;
#pragma unroll
        for (int nt = 0; nt < 8; ++nt) {
            tm0 = fmaxf(tm0, fmaxf(s[nt][0], s[nt][1]));
            tm1 = fmaxf(tm1, fmaxf(s[nt][2], s[nt][3]));
        }
        tm0 = fmaxf(tm0, __shfl_xor_sync(0xffffffffu, tm0, 1));
        tm0 = fmaxf(tm0, __shfl_xor_sync(0xffffffffu, tm0, 2));
        tm1 = fmaxf(tm1, __shfl_xor_sync(0xffffffffu, tm1, 1));
        tm1 = fmaxf(tm1, __shfl_xor_sync(0xffffffffu, tm1, 2));
        float mn0 = fmaxf(m0r, tm0), mn1 = fmaxf(m1r, tm1);
        float al0 = __expf(m0r - mn0), al1 = __expf(m1r - mn1);
        m0r = mn0; m1r = mn1;
        float rs0 = 0.f, rs1 = 0.f;
#pragma unroll
        for (int nt = 0; nt < 8; ++nt) {
            s[nt][0] = __expf(s[nt][0] - mn0); rs0 += s[nt][0];
            s[nt][1] = __expf(s[nt][1] - mn0); rs0 += s[nt][1];
            s[nt][2] = __expf(s[nt][2] - mn1); rs1 += s[nt][2];
            s[nt][3] = __expf(s[nt][3] - mn1); rs1 += s[nt][3];
        }
        rs0 += __shfl_xor_sync(0xffffffffu, rs0, 1);
        rs0 += __shfl_xor_sync(0xffffffffu, rs0, 2);
        rs1 += __shfl_xor_sync(0xffffffffu, rs1, 1);
        rs1 += __shfl_xor_sync(0xffffffffu, rs1, 2);
        l0 = l0 * al0 + rs0;
        l1 = l1 * al1 + rs1;
#pragma unroll
        for (int dn = 0; dn < 8; ++dn) {
            oa[dn][0] *= al0; oa[dn][1] *= al0;
            oa[dn][2] *= al1; oa[dn][3] *= al1;
        }

        // write P to warp-private slice of Ps[key][q]
#pragma unroll
        for (int nt = 0; nt < 8; ++nt) {
            Ps[nt * 8 + 2 * t][warp * 16 + g]         = f2tf(s[nt][0]);
            Ps[nt * 8 + 2 * t + 1][warp * 16 + g]     = f2tf(s[nt][1]);
            Ps[nt * 8 + 2 * t][warp * 16 + g + 8]     = f2tf(s[nt][2]);
            Ps[nt * 8 + 2 * t + 1][warp * 16 + g + 8] = f2tf(s[nt][3]);
        }
        __syncwarp();

        // O += P @ V
#pragma unroll
        for (int ks = 0; ks < 8; ++ks) {
            unsigned pa[4] = {Ps[ks * 8 + t][warp * 16 + g],
                              Ps[ks * 8 + t][warp * 16 + g + 8],
                              Ps[ks * 8 + t + 4][warp * 16 + g],
                              Ps[ks * 8 + t + 4][warp * 16 + g + 8]};
#pragma unroll
            for (int dn = 0; dn < 8; ++dn) {
                unsigned bf[2] = {Vs[ks * 8 + t][dn * 8 + g],
                                  Vs[ks * 8 + t + 4][dn * 8 + g]};
                mma8(oa[dn], pa, bf);
            }
        }
        __syncthreads();   // Ks/Vs reads done before next tile's staging
    }

    float i0 = 1.f / l0, i1 = 1.f / l1;
    int row0 = q0 + warp * 16 + g;
#pragma unroll
    for (int dn = 0; dn < 8; ++dn) {
        int col = dn * 8 + 2 * t;
        *(float2*)&Op[(size_t)row0 * OUT_C + col] =
            make_float2(oa[dn][0] * i0, oa[dn][1] * i0);
        *(float2*)&Op[(size_t)(row0 + 8) * OUT_C + col] =
            make_float2(oa[dn][2] * i1, oa[dn][3] * i1);
    }
}

// ---------------- mix + LayerNorm -------------------------------------------
__global__ __launch_bounds__(256) void mixln_kernel(
    const float* __restrict__ wmix, const float* __restrict__ ln_g,
    const float* __restrict__ ln_b)
{
    int row = blockIdx.x;
    const float* a0 = &g_att[0][0][0][0] + (size_t)row * OUT_C;
    const float* a1 = &g_att[1][0][0][0] + (size_t)row * OUT_C;
    float wm = *wmix;
    int tid = threadIdx.x;

    float v[8];
    float sum = 0.f, sq = 0.f;
#pragma unroll
    for (int k = 0; k < 8; ++k) {
        int c = tid + k * 256;
        float x = a1[c] * wm + a0[c] * (1.f - wm);
        v[k] = x; sum += x; sq += x * x;
    }
#pragma unroll
    for (int off = 16; off; off >>= 1) {
        sum += __shfl_xor_sync(0xffffffffu, sum, off);
        sq  += __shfl_xor_sync(0xffffffffu, sq,  off);
    }
    __shared__ float red[2][8];
    if ((tid & 31) == 0) { red[0][tid >> 5] = sum; red[1][tid >> 5] = sq; }
    __syncthreads();
    float ts = 0.f, t2 = 0.f;
#pragma unroll
    for (int w2 = 0; w2 < 8; ++w2) { ts += red[0][w2]; t2 += red[1][w2]; }
    float mu   = ts * (1.f / 2048.f);
    float var  = t2 * (1.f / 2048.f) - mu * mu;
    float rstd = rsqrtf(var + 1e-5f);
#pragma unroll
    for (int k = 0; k < 8; ++k) {
        int c = tid + k * 256;
        g_r[row][c] = (v[k] - mu) * rstd * ln_g[c] + ln_b[c];
    }
}

// ---------------- final transpose -------------------------------------------
__global__ void transpose_out(float* __restrict__ out)
{
    __shared__ float tile[32][33];
    int b  = blockIdx.z;
    int o0 = blockIdx.x * 32, t0 = blockIdx.y * 32;
    int tx2 = threadIdx.x, ty2 = threadIdx.y;
#pragma unroll
    for (int r = 0; r < 4; ++r)
        tile[ty2 + r * 8][tx2] = g_fc[(size_t)b * TT + t0 + ty2 + r * 8][o0 + tx2];
    __syncthreads();
#pragma unroll
    for (int r = 0; r < 4; ++r)
        out[((size_t)b * OUT_C + o0 + ty2 + r * 8) * TT + t0 + tx2] =
            tile[tx2][ty2 + r * 8];
}

// ---------------- launch ----------------------------------------------------
extern "C" void kernel_launch(void* const* d_in, const int* in_sizes, int n_in,
                              void* d_out, int out_size)
{
    const float* x_cnn = (const float*)d_in[0];
    const float* x_vit = (const float*)d_in[1];
    const float* Wq    = (const float*)d_in[2];
    const float* bq    = (const float*)d_in[3];
    const float* Wk    = (const float*)d_in[4];
    const float* bk    = (const float*)d_in[5];
    const float* Wv    = (const float*)d_in[6];
    const float* bv    = (const float*)d_in[7];
    const float* w_mix = (const float*)d_in[8];
    const float* ln_g  = (const float*)d_in[9];
    const float* ln_b  = (const float*)d_in[10];
    const float* Wfc   = (const float*)d_in[11];
    const float* bfc   = (const float*)d_in[12];
    float* out = (float*)d_out;

    const int ATT_SMEM = (2 * 64 * 72 + 64 * 136) * (int)sizeof(unsigned); // 71680
    cudaFuncSetAttribute(attn_tc,
                         cudaFuncAttributeMaxDynamicSharedMemorySize, ATT_SMEM);

    proj_gemm_tc<<<dim3(16, 8, 48), 256>>>(x_cnn, x_vit, Wq, bq, Wk, bk, Wv, bv);
    attn_tc<<<dim3(8, 32, 16), 256, ATT_SMEM>>>();
    mixln_kernel<<<NB * TT, 256>>>(w_mix, ln_g, ln_b);
    fc_gemm_tc<<<dim3(16, 64), 256>>>(Wfc, bfc);
    transpose_out<<<dim3(64, 32, 8), dim3(32, 8)>>>(out);
}

// round 7
// speedup vs baseline: 3.2958x; 2.1898x over previous
#include <cuda_runtime.h>

#define CC    1024
#define TT    1024
#define OUT_C 2048
#define NB    8
#define NH    32
#define HD    64

// ---------------- scratch (static device globals) ----------------------------
__device__ float    g_qkv[2][3][NB][TT][OUT_C];
__device__ float    g_att[2][NB][TT][OUT_C];
__device__ unsigned g_rtf[NB * TT][OUT_C];          // LN output, tf32 bits
__device__ float    g_fc[NB * TT][OUT_C];
__device__ unsigned g_xtf[2][NB][CC][TT];           // inputs as tf32 (k-major)
__device__ unsigned g_wt[3][CC][OUT_C];             // Wq/Wk/Wv transposed, tf32
__device__ unsigned g_wfct[OUT_C][OUT_C];           // Wfc transposed, tf32

// ---------------- helpers ----------------------------------------------------
__device__ __forceinline__ unsigned f2tf(float x) {
    unsigned r;
    asm("cvt.rna.tf32.f32 %0, %1;" : "=r"(r) : "f"(x));
    return r;
}

__device__ __forceinline__ void mma8(float* d, const unsigned* a, const unsigned* b) {
    asm volatile(
        "mma.sync.aligned.m16n8k8.row.col.f32.tf32.tf32.f32 "
        "{%0,%1,%2,%3}, {%4,%5,%6,%7}, {%8,%9}, {%0,%1,%2,%3};"
        : "+f"(d[0]), "+f"(d[1]), "+f"(d[2]), "+f"(d[3])
        : "r"(a[0]), "r"(a[1]), "r"(a[2]), "r"(a[3]), "r"(b[0]), "r"(b[1]));
}

__device__ __forceinline__ void cpa16(void* d, const void* s) {
    unsigned sa = (unsigned)__cvta_generic_to_shared(d);
    asm volatile("cp.async.cg.shared.global [%0], [%1], 16;" :: "r"(sa), "l"(s));
}
__device__ __forceinline__ void cp_commit() {
    asm volatile("cp.async.commit_group;");
}
template <int N> __device__ __forceinline__ void cp_wait() {
    asm volatile("cp.async.wait_group %0;" :: "n"(N));
}

// ---------------- prolog converts --------------------------------------------
__global__ void ecvt(const float4* __restrict__ src, uint4* __restrict__ dst, int n4)
{
    int i = blockIdx.x * blockDim.x + threadIdx.x;
    if (i < n4) {
        float4 v = src[i];
        dst[i] = make_uint4(f2tf(v.x), f2tf(v.y), f2tf(v.z), f2tf(v.w));
    }
}

// dst[c][r] = tf32(src[r][c]); src is [R][Cd]
__global__ void tcvt(const float* __restrict__ src, unsigned* __restrict__ dst,
                     int R, int Cd)
{
    __shared__ unsigned tile[32][33];
    int c0 = blockIdx.x * 32, r0 = blockIdx.y * 32;
    int tx = threadIdx.x, ty = threadIdx.y;   // (32, 8)
#pragma unroll
    for (int i = 0; i < 4; ++i)
        tile[ty + i * 8][tx] = f2tf(src[(size_t)(r0 + ty + i * 8) * Cd + c0 + tx]);
    __syncthreads();
#pragma unroll
    for (int i = 0; i < 4; ++i)
        dst[(size_t)(c0 + ty + i * 8) * R + r0 + tx] = tile[tx][ty + i * 8];
}

// ---------------- projection GEMM: cp.async 3-stage, tf32 --------------------
// A = g_xtf[s][b] ([C][T] k-major), B = g_wt[w] ([C][OUT] k-major).
__global__ __launch_bounds__(256, 2) void proj_gemm_tc(
    const float* __restrict__ bq, const float* __restrict__ bk,
    const float* __restrict__ bv)
{
    extern __shared__ unsigned sm[];
    unsigned (*As)[16][136] = (unsigned(*)[16][136])sm;               // [3][16][136]
    unsigned (*Bs)[16][136] = (unsigned(*)[16][136])(sm + 3 * 16 * 136);

    int z = blockIdx.z;
    int w  = z % 3;
    int sb = z / 3;
    int s = sb >> 3, b = sb & 7;
    const unsigned* X  = &g_xtf[s][b][0][0];
    const unsigned* Wt = &g_wt[w][0][0];
    const float*    bp = (w == 0) ? bq : ((w == 1) ? bk : bv);
    float* Cout = &g_qkv[s][w][b][0][0];

    int tid  = threadIdx.x;
    int warp = tid >> 5, lane = tid & 31;
    int g = lane >> 2, t = lane & 3;
    int wm = warp >> 2, wn = warp & 3;
    int m0 = blockIdx.y * 128;
    int n0 = blockIdx.x * 128;

    int sk = tid >> 4;              // 0..15 k-row
    int sc = (tid & 15) << 3;       // 0..120, 8 cols

    float acc[4][4][4] = {};

    const int NT = CC / 16;
    // prologue: stages 0, 1
#pragma unroll
    for (int st = 0; st < 2; ++st) {
        const unsigned* ap = X  + (size_t)(st * 16 + sk) * TT    + m0 + sc;
        const unsigned* bp2 = Wt + (size_t)(st * 16 + sk) * OUT_C + n0 + sc;
        cpa16(&As[st][sk][sc], ap);      cpa16(&As[st][sk][sc + 4], ap + 4);
        cpa16(&Bs[st][sk][sc], bp2);     cpa16(&Bs[st][sk][sc + 4], bp2 + 4);
        cp_commit();
    }

    for (int kt = 0; kt < NT; ++kt) {
        if (kt == NT - 1) cp_wait<0>(); else cp_wait<1>();
        __syncthreads();
        int cur = kt % 3;
#pragma unroll
        for (int kk = 0; kk < 2; ++kk) {
            int k0 = kk * 8;
            unsigned af[4][4], bf[4][2];
#pragma unroll
            for (int mi = 0; mi < 4; ++mi) {
                int m = wm * 64 + mi * 16 + g;
                af[mi][0] = As[cur][k0 + t][m];
                af[mi][1] = As[cur][k0 + t][m + 8];
                af[mi][2] = As[cur][k0 + t + 4][m];
                af[mi][3] = As[cur][k0 + t + 4][m + 8];
            }
#pragma unroll
            for (int ni = 0; ni < 4; ++ni) {
                int n = wn * 32 + ni * 8 + g;
                bf[ni][0] = Bs[cur][k0 + t][n];
                bf[ni][1] = Bs[cur][k0 + t + 4][n];
            }
#pragma unroll
            for (int mi = 0; mi < 4; ++mi)
#pragma unroll
                for (int ni = 0; ni < 4; ++ni)
                    mma8(acc[mi][ni], af[mi], bf[ni]);
        }
        if (kt + 2 < NT) {
            int st = (kt + 2) % 3;
            int kb = (kt + 2) * 16;
            const unsigned* ap  = X  + (size_t)(kb + sk) * TT    + m0 + sc;
            const unsigned* bp2 = Wt + (size_t)(kb + sk) * OUT_C + n0 + sc;
            cpa16(&As[st][sk][sc], ap);  cpa16(&As[st][sk][sc + 4], ap + 4);
            cpa16(&Bs[st][sk][sc], bp2); cpa16(&Bs[st][sk][sc + 4], bp2 + 4);
            cp_commit();
        }
    }

#pragma unroll
    for (int mi = 0; mi < 4; ++mi) {
#pragma unroll
        for (int ni = 0; ni < 4; ++ni) {
            int row = m0 + wm * 64 + mi * 16 + g;
            int col = n0 + wn * 32 + ni * 8 + 2 * t;
            float b0 = bp[col], b1 = bp[col + 1];
            float* c0 = Cout + (size_t)row * OUT_C + col;
            float* c1 = Cout + (size_t)(row + 8) * OUT_C + col;
            *(float2*)c0 = make_float2(acc[mi][ni][0] + b0, acc[mi][ni][1] + b1);
            *(float2*)c1 = make_float2(acc[mi][ni][2] + b0, acc[mi][ni][3] + b1);
        }
    }
}

// ---------------- FC GEMM: cp.async 3-stage, tf32 ----------------------------
// A = g_rtf ([M][K] row-major, stride-20 smem), B = g_wfct ([K][OUT] k-major).
__global__ __launch_bounds__(256, 2) void fc_gemm_tc(const float* __restrict__ bfc)
{
    extern __shared__ unsigned sm[];
    unsigned (*A2)[128][20]  = (unsigned(*)[128][20])sm;              // [3][128][20]
    unsigned (*Bs)[16][136]  = (unsigned(*)[16][136])(sm + 3 * 128 * 20);

    const unsigned* A  = &g_rtf[0][0];
    const unsigned* Wt = &g_wfct[0][0];

    int tid  = threadIdx.x;
    int warp = tid >> 5, lane = tid & 31;
    int g = lane >> 2, t = lane & 3;
    int wm = warp >> 2, wn = warp & 3;
    int m0 = blockIdx.y * 128;
    int n0 = blockIdx.x * 128;

    int ar = tid & 127;             // A row 0..127
    int akk = (tid >> 7) << 3;      // 0 or 8 (k offset)
    int sk = tid >> 4;              // B k-row 0..15
    int sc = (tid & 15) << 3;       // B col, 8 words

    float acc[4][4][4] = {};

    const int NT = OUT_C / 16;
#pragma unroll
    for (int st = 0; st < 2; ++st) {
        const unsigned* ap  = A  + (size_t)(m0 + ar) * OUT_C + st * 16 + akk;
        const unsigned* bp2 = Wt + (size_t)(st * 16 + sk) * OUT_C + n0 + sc;
        cpa16(&A2[st][ar][akk], ap);   cpa16(&A2[st][ar][akk + 4], ap + 4);
        cpa16(&Bs[st][sk][sc], bp2);   cpa16(&Bs[st][sk][sc + 4], bp2 + 4);
        cp_commit();
    }

    for (int kt = 0; kt < NT; ++kt) {
        if (kt == NT - 1) cp_wait<0>(); else cp_wait<1>();
        __syncthreads();
        int cur = kt % 3;
#pragma unroll
        for (int kk = 0; kk < 2; ++kk) {
            int k0 = kk * 8;
            unsigned af[4][4], bf[4][2];
#pragma unroll
            for (int mi = 0; mi < 4; ++mi) {
                int m = wm * 64 + mi * 16 + g;
                af[mi][0] = A2[cur][m][k0 + t];
                af[mi][1] = A2[cur][m + 8][k0 + t];
                af[mi][2] = A2[cur][m][k0 + t + 4];
                af[mi][3] = A2[cur][m + 8][k0 + t + 4];
            }
#pragma unroll
            for (int ni = 0; ni < 4; ++ni) {
                int n = wn * 32 + ni * 8 + g;
                bf[ni][0] = Bs[cur][k0 + t][n];
                bf[ni][1] = Bs[cur][k0 + t + 4][n];
            }
#pragma unroll
            for (int mi = 0; mi < 4; ++mi)
#pragma unroll
                for (int ni = 0; ni < 4; ++ni)
                    mma8(acc[mi][ni], af[mi], bf[ni]);
        }
        if (kt + 2 < NT) {
            int st = (kt + 2) % 3;
            int kb = (kt + 2) * 16;
            const unsigned* ap  = A  + (size_t)(m0 + ar) * OUT_C + kb + akk;
            const unsigned* bp2 = Wt + (size_t)(kb + sk) * OUT_C + n0 + sc;
            cpa16(&A2[st][ar][akk], ap);  cpa16(&A2[st][ar][akk + 4], ap + 4);
            cpa16(&Bs[st][sk][sc], bp2);  cpa16(&Bs[st][sk][sc + 4], bp2 + 4);
            cp_commit();
        }
    }

#pragma unroll
    for (int mi = 0; mi < 4; ++mi) {
#pragma unroll
        for (int ni = 0; ni < 4; ++ni) {
            int row = m0 + wm * 64 + mi * 16 + g;
            int col = n0 + wn * 32 + ni * 8 + 2 * t;
            float b0 = bfc[col], b1 = bfc[col + 1];
            *(float2*)&g_fc[row][col] =
                make_float2(acc[mi][ni][0] + b0, acc[mi][ni][1] + b1);
            *(float2*)&g_fc[row + 8][col] =
                make_float2(acc[mi][ni][2] + b0, acc[mi][ni][3] + b1);
        }
    }
}

// ---------------- flash attention on tf32 tensor cores (unchanged) -----------
__global__ __launch_bounds__(256, 2) void attn_tc()
{
    extern __shared__ unsigned smext[];
    unsigned (*Ks)[72]  = (unsigned(*)[72]) smext;
    unsigned (*Vs)[72]  = (unsigned(*)[72])(smext + 64 * 72);
    unsigned (*Ps)[136] = (unsigned(*)[136])(smext + 2 * 64 * 72);

    int qt = blockIdx.x, h = blockIdx.y, z = blockIdx.z;
    int dir = z >> 3, b = z & 7;
    int skv = 1 - dir;
    const float* Qp = &g_qkv[dir][0][b][0][h * HD];
    const float* Kp = &g_qkv[skv][1][b][0][h * HD];
    const float* Vp = &g_qkv[skv][2][b][0][h * HD];
    float*       Op = &g_att[dir][b][0][h * HD];

    int tid  = threadIdx.x;
    int warp = tid >> 5, lane = tid & 31;
    int g = lane >> 2, t = lane & 3;
    int q0 = qt * 128;

    {
        int q  = tid >> 1;
        int dl = (tid & 1) * 4;
#pragma unroll
        for (int p = 0; p < 8; ++p) {
            int d = p * 8 + dl;
            float4 v = *(const float4*)&Qp[(size_t)(q0 + q) * OUT_C + d];
            Ps[d + 0][q] = f2tf(v.x * 0.03125f);
            Ps[d + 1][q] = f2tf(v.y * 0.03125f);
            Ps[d + 2][q] = f2tf(v.z * 0.03125f);
            Ps[d + 3][q] = f2tf(v.w * 0.03125f);
        }
    }
    __syncthreads();
    unsigned qa[8][4];
#pragma unroll
    for (int ks = 0; ks < 8; ++ks) {
        qa[ks][0] = Ps[ks * 8 + t][warp * 16 + g];
        qa[ks][1] = Ps[ks * 8 + t][warp * 16 + g + 8];
        qa[ks][2] = Ps[ks * 8 + t + 4][warp * 16 + g];
        qa[ks][3] = Ps[ks * 8 + t + 4][warp * 16 + g + 8];
    }
    __syncthreads();

    float m0r = -1e30f, m1r = -1e30f, l0 = 0.f, l1 = 0.f;
    float oa[8][4] = {};

    for (int kt = 0; kt < TT / 64; ++kt) {
        {
            int key = tid >> 2;
            int dl  = (tid & 3) * 4;
            const float* kRow = Kp + (size_t)(kt * 64 + key) * OUT_C;
            const float* vRow = Vp + (size_t)(kt * 64 + key) * OUT_C;
#pragma unroll
            for (int p = 0; p < 4; ++p) {
                int d = p * 16 + dl;
                float4 kv = *(const float4*)&kRow[d];
                Ks[d + 0][key] = f2tf(kv.x);
                Ks[d + 1][key] = f2tf(kv.y);
                Ks[d + 2][key] = f2tf(kv.z);
                Ks[d + 3][key] = f2tf(kv.w);
                float4 vv = *(const float4*)&vRow[d];
                Vs[key][d + 0] = f2tf(vv.x);
                Vs[key][d + 1] = f2tf(vv.y);
                Vs[key][d + 2] = f2tf(vv.z);
                Vs[key][d + 3] = f2tf(vv.w);
            }
        }
        __syncthreads();

        float s[8][4] = {};
#pragma unroll
        for (int ks = 0; ks < 8; ++ks) {
#pragma unroll
            for (int nt = 0; nt < 8; ++nt) {
                unsigned bf[2] = {Ks[ks * 8 + t][nt * 8 + g],
                                  Ks[ks * 8 + t + 4][nt * 8 + g]};
                mma8(s[nt], qa[ks], bf);
            }
        }

        float tm0 = -1e30f, tm1 = -1e30f;
#pragma unroll
        for (int nt = 0; nt < 8; ++nt) {
            tm0 = fmaxf(tm0, fmaxf(s[nt][0], s[nt][1]));
            tm1 = fmaxf(tm1, fmaxf(s[nt][2], s[nt][3]));
        }
        tm0 = fmaxf(tm0, __shfl_xor_sync(0xffffffffu, tm0, 1));
        tm0 = fmaxf(tm0, __shfl_xor_sync(0xffffffffu, tm0, 2));
        tm1 = fmaxf(tm1, __shfl_xor_sync(0xffffffffu, tm1, 1));
        tm1 = fmaxf(tm1, __shfl_xor_sync(0xffffffffu, tm1, 2));
        float mn0 = fmaxf(m0r, tm0), mn1 = fmaxf(m1r, tm1);
        float al0 = __expf(m0r - mn0), al1 = __expf(m1r - mn1);
        m0r = mn0; m1r = mn1;
        float rs0 = 0.f, rs1 = 0.f;
#pragma unroll
        for (int nt = 0; nt < 8; ++nt) {
            s[nt][0] = __expf(s[nt][0] - mn0); rs0 += s[nt][0];
            s[nt][1] = __expf(s[nt][1] - mn0); rs0 += s[nt][1];
            s[nt][2] = __expf(s[nt][2] - mn1); rs1 += s[nt][2];
            s[nt][3] = __expf(s[nt][3] - mn1); rs1 += s[nt][3];
        }
        rs0 += __shfl_xor_sync(0xffffffffu, rs0, 1);
        rs0 += __shfl_xor_sync(0xffffffffu, rs0, 2);
        rs1 += __shfl_xor_sync(0xffffffffu, rs1, 1);
        rs1 += __shfl_xor_sync(0xffffffffu, rs1, 2);
        l0 = l0 * al0 + rs0;
        l1 = l1 * al1 + rs1;
#pragma unroll
        for (int dn = 0; dn < 8; ++dn) {
            oa[dn][0] *= al0; oa[dn][1] *= al0;
            oa[dn][2] *= al1; oa[dn][3] *= al1;
        }

#pragma unroll
        for (int nt = 0; nt < 8; ++nt) {
            Ps[nt * 8 + 2 * t][warp * 16 + g]         = f2tf(s[nt][0]);
            Ps[nt * 8 + 2 * t + 1][warp * 16 + g]     = f2tf(s[nt][1]);
            Ps[nt * 8 + 2 * t][warp * 16 + g + 8]     = f2tf(s[nt][2]);
            Ps[nt * 8 + 2 * t + 1][warp * 16 + g + 8] = f2tf(s[nt][3]);
        }
        __syncwarp();

#pragma unroll
        for (int ks = 0; ks < 8; ++ks) {
            unsigned pa[4] = {Ps[ks * 8 + t][warp * 16 + g],
                              Ps[ks * 8 + t][warp * 16 + g + 8],
                              Ps[ks * 8 + t + 4][warp * 16 + g],
                              Ps[ks * 8 + t + 4][warp * 16 + g + 8]};
#pragma unroll
            for (int dn = 0; dn < 8; ++dn) {
                unsigned bf[2] = {Vs[ks * 8 + t][dn * 8 + g],
                                  Vs[ks * 8 + t + 4][dn * 8 + g]};
                mma8(oa[dn], pa, bf);
            }
        }
        __syncthreads();
    }

    float i0 = 1.f / l0, i1 = 1.f / l1;
    int row0 = q0 + warp * 16 + g;
#pragma unroll
    for (int dn = 0; dn < 8; ++dn) {
        int col = dn * 8 + 2 * t;
        *(float2*)&Op[(size_t)row0 * OUT_C + col] =
            make_float2(oa[dn][0] * i0, oa[dn][1] * i0);
        *(float2*)&Op[(size_t)(row0 + 8) * OUT_C + col] =
            make_float2(oa[dn][2] * i1, oa[dn][3] * i1);
    }
}

// ---------------- mix + LayerNorm (emits tf32 for fc) ------------------------
__global__ __launch_bounds__(256) void mixln_kernel(
    const float* __restrict__ wmix, const float* __restrict__ ln_g,
    const float* __restrict__ ln_b)
{
    int row = blockIdx.x;
    const float* a0 = &g_att[0][0][0][0] + (size_t)row * OUT_C;
    const float* a1 = &g_att[1][0][0][0] + (size_t)row * OUT_C;
    float wm = *wmix;
    int tid = threadIdx.x;

    float v[8];
    float sum = 0.f, sq = 0.f;
#pragma unroll
    for (int k = 0; k < 8; ++k) {
        int c = tid + k * 256;
        float x = a1[c] * wm + a0[c] * (1.f - wm);
        v[k] = x; sum += x; sq += x * x;
    }
#pragma unroll
    for (int off = 16; off; off >>= 1) {
        sum += __shfl_xor_sync(0xffffffffu, sum, off);
        sq  += __shfl_xor_sync(0xffffffffu, sq,  off);
    }
    __shared__ float red[2][8];
    if ((tid & 31) == 0) { red[0][tid >> 5] = sum; red[1][tid >> 5] = sq; }
    __syncthreads();
    float ts = 0.f, t2 = 0.f;
#pragma unroll
    for (int w2 = 0; w2 < 8; ++w2) { ts += red[0][w2]; t2 += red[1][w2]; }
    float mu   = ts * (1.f / 2048.f);
    float var  = t2 * (1.f / 2048.f) - mu * mu;
    float rstd = rsqrtf(var + 1e-5f);
#pragma unroll
    for (int k = 0; k < 8; ++k) {
        int c = tid + k * 256;
        g_rtf[row][c] = f2tf((v[k] - mu) * rstd * ln_g[c] + ln_b[c]);
    }
}

// ---------------- final transpose -------------------------------------------
__global__ void transpose_out(float* __restrict__ out)
{
    __shared__ float tile[32][33];
    int b  = blockIdx.z;
    int o0 = blockIdx.x * 32, t0 = blockIdx.y * 32;
    int tx2 = threadIdx.x, ty2 = threadIdx.y;
#pragma unroll
    for (int r = 0; r < 4; ++r)
        tile[ty2 + r * 8][tx2] = g_fc[(size_t)b * TT + t0 + ty2 + r * 8][o0 + tx2];
    __syncthreads();
#pragma unroll
    for (int r = 0; r < 4; ++r)
        out[((size_t)b * OUT_C + o0 + ty2 + r * 8) * TT + t0 + tx2] =
            tile[tx2][ty2 + r * 8];
}

// ---------------- launch ----------------------------------------------------
extern "C" void kernel_launch(void* const* d_in, const int* in_sizes, int n_in,
                              void* d_out, int out_size)
{
    const float* x_cnn = (const float*)d_in[0];
    const float* x_vit = (const float*)d_in[1];
    const float* Wq    = (const float*)d_in[2];
    const float* bq    = (const float*)d_in[3];
    const float* Wk    = (const float*)d_in[4];
    const float* bk    = (const float*)d_in[5];
    const float* Wv    = (const float*)d_in[6];
    const float* bv    = (const float*)d_in[7];
    const float* w_mix = (const float*)d_in[8];
    const float* ln_g  = (const float*)d_in[9];
    const float* ln_b  = (const float*)d_in[10];
    const float* Wfc   = (const float*)d_in[11];
    const float* bfc   = (const float*)d_in[12];
    float* out = (float*)d_out;

    const int ATT_SMEM  = (2 * 64 * 72 + 64 * 136) * (int)sizeof(unsigned); // 71680
    const int PROJ_SMEM = 3 * 2 * 16 * 136 * (int)sizeof(unsigned);         // 52224
    const int FC_SMEM   = 3 * (128 * 20 + 16 * 136) * (int)sizeof(unsigned);// 56832
    cudaFuncSetAttribute(attn_tc,      cudaFuncAttributeMaxDynamicSharedMemorySize, ATT_SMEM);
    cudaFuncSetAttribute(proj_gemm_tc, cudaFuncAttributeMaxDynamicSharedMemorySize, PROJ_SMEM);
    cudaFuncSetAttribute(fc_gemm_tc,   cudaFuncAttributeMaxDynamicSharedMemorySize, FC_SMEM);

    unsigned* xtf  = 0;  cudaGetSymbolAddress((void**)&xtf,  g_xtf);
    unsigned* wt   = 0;  cudaGetSymbolAddress((void**)&wt,   g_wt);
    unsigned* wfct = 0;  cudaGetSymbolAddress((void**)&wfct, g_wfct);

    // prolog: tf32 pre-conversion of all GEMM operands
    const int NX4 = NB * CC * TT / 4;   // 2M float4 per source
    ecvt<<<(NX4 + 255) / 256, 256>>>((const float4*)x_cnn, (uint4*)xtf, NX4);
    ecvt<<<(NX4 + 255) / 256, 256>>>((const float4*)x_vit,
                                     (uint4*)(xtf + (size_t)NB * CC * TT), NX4);
    tcvt<<<dim3(CC / 32, OUT_C / 32), dim3(32, 8)>>>(Wq, wt, OUT_C, CC);
    tcvt<<<dim3(CC / 32, OUT_C / 32), dim3(32, 8)>>>(Wk, wt + (size_t)CC * OUT_C, OUT_C, CC);
    tcvt<<<dim3(CC / 32, OUT_C / 32), dim3(32, 8)>>>(Wv, wt + 2 * (size_t)CC * OUT_C, OUT_C, CC);
    tcvt<<<dim3(OUT_C / 32, OUT_C / 32), dim3(32, 8)>>>(Wfc, wfct, OUT_C, OUT_C);

    proj_gemm_tc<<<dim3(16, 8, 48), 256, PROJ_SMEM>>>(bq, bk, bv);
    attn_tc<<<dim3(8, 32, 16), 256, ATT_SMEM>>>();
    mixln_kernel<<<NB * TT, 256>>>(w_mix, ln_g, ln_b);
    fc_gemm_tc<<<dim3(16, 64), 256, FC_SMEM>>>(bfc);
    transpose_out<<<dim3(64, 32, 8), dim3(32, 8)>>>(out);
}

// round 10
// speedup vs baseline: 3.6370x; 1.1035x over previous
#include <cuda_runtime.h>

#define CC    1024
#define TT    1024
#define OUT_C 2048
#define NB    8
#define NH    32
#define HD    64

// ---------------- scratch (static device globals) ----------------------------
__device__ unsigned g_qT[2][NB][OUT_C][TT];   // Q transposed, tf32, pre-scaled 1/32
__device__ unsigned g_kT[2][NB][OUT_C][TT];   // K transposed, tf32
__device__ unsigned g_v [2][NB][TT][OUT_C];   // V normal, tf32
__device__ float    g_att[2][NB][TT][OUT_C];
__device__ unsigned g_rtf[NB * TT][OUT_C];    // LN output, tf32 bits
__device__ unsigned g_xtf[2][NB][CC][TT];     // inputs as tf32 (k-major)
__device__ unsigned g_wt[3][CC][OUT_C];       // Wq/Wk/Wv transposed, tf32
__device__ unsigned g_wfct[OUT_C][OUT_C];     // Wfc transposed, tf32

// ---------------- helpers ----------------------------------------------------
__device__ __forceinline__ unsigned f2tf(float x) {
    unsigned r;
    asm("cvt.rna.tf32.f32 %0, %1;" : "=r"(r) : "f"(x));
    return r;
}

__device__ __forceinline__ void mma8(float* d, const unsigned* a, const unsigned* b) {
    asm volatile(
        "mma.sync.aligned.m16n8k8.row.col.f32.tf32.tf32.f32 "
        "{%0,%1,%2,%3}, {%4,%5,%6,%7}, {%8,%9}, {%0,%1,%2,%3};"
        : "+f"(d[0]), "+f"(d[1]), "+f"(d[2]), "+f"(d[3])
        : "r"(a[0]), "r"(a[1]), "r"(a[2]), "r"(a[3]), "r"(b[0]), "r"(b[1]));
}

__device__ __forceinline__ void cpa16(void* d, const void* s) {
    unsigned sa = (unsigned)__cvta_generic_to_shared(d);
    asm volatile("cp.async.cg.shared.global [%0], [%1], 16;" :: "r"(sa), "l"(s));
}
__device__ __forceinline__ void cp_commit() {
    asm volatile("cp.async.commit_group;");
}
template <int N> __device__ __forceinline__ void cp_wait() {
    asm volatile("cp.async.wait_group %0;" :: "n"(N));
}

// ---------------- prolog converts --------------------------------------------
__global__ void ecvt(const float4* __restrict__ src, uint4* __restrict__ dst, int n4)
{
    int i = blockIdx.x * blockDim.x + threadIdx.x;
    if (i < n4) {
        float4 v = src[i];
        dst[i] = make_uint4(f2tf(v.x), f2tf(v.y), f2tf(v.z), f2tf(v.w));
    }
}

// dst[c][r] = tf32(src[r][c]); src is [R][Cd]
__global__ void tcvt(const float* __restrict__ src, unsigned* __restrict__ dst,
                     int R, int Cd)
{
    __shared__ unsigned tile[32][33];
    int c0 = blockIdx.x * 32, r0 = blockIdx.y * 32;
    int tx = threadIdx.x, ty = threadIdx.y;   // (32, 8)
#pragma unroll
    for (int i = 0; i < 4; ++i)
        tile[ty + i * 8][tx] = f2tf(src[(size_t)(r0 + ty + i * 8) * Cd + c0 + tx]);
    __syncthreads();
#pragma unroll
    for (int i = 0; i < 4; ++i)
        dst[(size_t)(c0 + ty + i * 8) * R + r0 + tx] = tile[tx][ty + i * 8];
}

// ---------------- projection GEMM: cp.async 4-stage, tf32 --------------------
// A = g_xtf[s][b] ([C][T] k-major), B = g_wt[w] ([C][OUT] k-major).
// Epilogue: Q/K written TRANSPOSED tf32 ([o][t], Q pre-scaled by 1/32),
//           V written normal tf32 ([t][o]).
__global__ __launch_bounds__(256, 2) void proj_gemm_tc(
    const float* __restrict__ bq, const float* __restrict__ bk,
    const float* __restrict__ bv)
{
    extern __shared__ unsigned sm[];
    unsigned (*As)[16][136] = (unsigned(*)[16][136])sm;               // [4][16][136]
    unsigned (*Bs)[16][136] = (unsigned(*)[16][136])(sm + 4 * 16 * 136);

    int z = blockIdx.z;
    int w  = z % 3;
    int sb = z / 3;
    int s = sb >> 3, b = sb & 7;
    const unsigned* X  = &g_xtf[s][b][0][0];
    const unsigned* Wt = &g_wt[w][0][0];
    const float*    bp = (w == 0) ? bq : ((w == 1) ? bk : bv);

    int tid  = threadIdx.x;
    int warp = tid >> 5, lane = tid & 31;
    int g = lane >> 2, t = lane & 3;
    int wm = warp >> 2, wn = warp & 3;
    int m0 = blockIdx.y * 128;
    int n0 = blockIdx.x * 128;

    int sk = tid >> 4;              // 0..15 k-row
    int sc = (tid & 15) << 3;       // 0..120, 8 cols

    float acc[4][4][4] = {};

    const int NT = CC / 16;
#pragma unroll
    for (int st = 0; st < 3; ++st) {
        const unsigned* ap  = X  + (size_t)(st * 16 + sk) * TT    + m0 + sc;
        const unsigned* bp2 = Wt + (size_t)(st * 16 + sk) * OUT_C + n0 + sc;
        cpa16(&As[st][sk][sc], ap);      cpa16(&As[st][sk][sc + 4], ap + 4);
        cpa16(&Bs[st][sk][sc], bp2);     cpa16(&Bs[st][sk][sc + 4], bp2 + 4);
        cp_commit();
    }

    for (int kt = 0; kt < NT; ++kt) {
        if (kt >= NT - 3) cp_wait<0>(); else cp_wait<2>();
        __syncthreads();
        int cur = kt & 3;
#pragma unroll
        for (int kk = 0; kk < 2; ++kk) {
            int k0 = kk * 8;
            unsigned af[4][4], bf[4][2];
#pragma unroll
            for (int mi = 0; mi < 4; ++mi) {
                int m = wm * 64 + mi * 16 + g;
                af[mi][0] = As[cur][k0 + t][m];
                af[mi][1] = As[cur][k0 + t][m + 8];
                af[mi][2] = As[cur][k0 + t + 4][m];
                af[mi][3] = As[cur][k0 + t + 4][m + 8];
            }
#pragma unroll
            for (int ni = 0; ni < 4; ++ni) {
                int n = wn * 32 + ni * 8 + g;
                bf[ni][0] = Bs[cur][k0 + t][n];
                bf[ni][1] = Bs[cur][k0 + t + 4][n];
            }
#pragma unroll
            for (int mi = 0; mi < 4; ++mi)
#pragma unroll
                for (int ni = 0; ni < 4; ++ni)
                    mma8(acc[mi][ni], af[mi], bf[ni]);
        }
        if (kt + 3 < NT) {
            int st = (kt + 3) & 3;
            int kb = (kt + 3) * 16;
            const unsigned* ap  = X  + (size_t)(kb + sk) * TT    + m0 + sc;
            const unsigned* bp2 = Wt + (size_t)(kb + sk) * OUT_C + n0 + sc;
            cpa16(&As[st][sk][sc], ap);  cpa16(&As[st][sk][sc + 4], ap + 4);
            cpa16(&Bs[st][sk][sc], bp2); cpa16(&Bs[st][sk][sc + 4], bp2 + 4);
            cp_commit();
        }
    }

    if (w == 2) {
        unsigned* Vout = &g_v[s][b][0][0];
#pragma unroll
        for (int mi = 0; mi < 4; ++mi) {
#pragma unroll
            for (int ni = 0; ni < 4; ++ni) {
                int row = m0 + wm * 64 + mi * 16 + g;
                int col = n0 + wn * 32 + ni * 8 + 2 * t;
                float b0 = bp[col], b1 = bp[col + 1];
                *(uint2*)&Vout[(size_t)row * OUT_C + col] =
                    make_uint2(f2tf(acc[mi][ni][0] + b0), f2tf(acc[mi][ni][1] + b1));
                *(uint2*)&Vout[(size_t)(row + 8) * OUT_C + col] =
                    make_uint2(f2tf(acc[mi][ni][2] + b0), f2tf(acc[mi][ni][3] + b1));
            }
        }
    } else {
        unsigned* Tout = (w == 0) ? &g_qT[s][b][0][0] : &g_kT[s][b][0][0];
        float sc2 = (w == 0) ? 0.03125f : 1.0f;
#pragma unroll
        for (int mi = 0; mi < 4; ++mi) {
#pragma unroll
            for (int ni = 0; ni < 4; ++ni) {
                int row = m0 + wm * 64 + mi * 16 + g;
                int col = n0 + wn * 32 + ni * 8 + 2 * t;
                float b0 = bp[col], b1 = bp[col + 1];
                Tout[(size_t)col * TT + row]           = f2tf((acc[mi][ni][0] + b0) * sc2);
                Tout[(size_t)(col + 1) * TT + row]     = f2tf((acc[mi][ni][1] + b1) * sc2);
                Tout[(size_t)col * TT + row + 8]       = f2tf((acc[mi][ni][2] + b0) * sc2);
                Tout[(size_t)(col + 1) * TT + row + 8] = f2tf((acc[mi][ni][3] + b1) * sc2);
            }
        }
    }
}

// ---------------- flash attention: tf32 mma + cp.async staged K/V ------------
__global__ __launch_bounds__(256, 2) void attn_tc()
{
    extern __shared__ unsigned smext[];
    unsigned (*Ps)[136]     = (unsigned(*)[136])smext;                  // Q then P
    unsigned (*Ks)[64][72]  = (unsigned(*)[64][72])(smext + 64 * 136);  // [2][64][72]
    unsigned (*Vs)[64][72]  = (unsigned(*)[64][72])(smext + 64 * 136 + 2 * 64 * 72);

    int qt = blockIdx.x, h = blockIdx.y, z = blockIdx.z;
    int dir = z >> 3, b = z & 7;
    int skv = 1 - dir;
    const unsigned* Qg = &g_qT[dir][b][h * HD][0];   // [64 d][1024 t]
    const unsigned* Kg = &g_kT[skv][b][h * HD][0];   // [64 d][1024 t]
    const unsigned* Vg = &g_v [skv][b][0][h * HD];   // [1024 t][2048 o] slice
    float*          Op = &g_att[dir][b][0][h * HD];

    int tid  = threadIdx.x;
    int warp = tid >> 5, lane = tid & 31;
    int g = lane >> 2, t = lane & 3;
    int q0 = qt * 128;

    // Q tile: 64 rows x 128 q = 2048 16B segments
#pragma unroll
    for (int i = 0; i < 8; ++i) {
        int j = tid + 256 * i;
        int row = j >> 5, seg = j & 31;
        cpa16(&Ps[row][seg * 4], Qg + (size_t)row * TT + q0 + seg * 4);
    }
    cp_commit();
    // K0 / V0 tiles: 64 rows x 64 cols each
#pragma unroll
    for (int i = 0; i < 4; ++i) {
        int j = tid + 256 * i;
        int row = j >> 4, seg = j & 15;
        cpa16(&Ks[0][row][seg * 4], Kg + (size_t)row * TT + seg * 4);
        cpa16(&Vs[0][row][seg * 4], Vg + (size_t)row * OUT_C + seg * 4);
    }
    cp_commit();

    cp_wait<0>();
    __syncthreads();

    unsigned qa[8][4];
#pragma unroll
    for (int ks = 0; ks < 8; ++ks) {
        qa[ks][0] = Ps[ks * 8 + t][warp * 16 + g];
        qa[ks][1] = Ps[ks * 8 + t][warp * 16 + g + 8];
        qa[ks][2] = Ps[ks * 8 + t + 4][warp * 16 + g];
        qa[ks][3] = Ps[ks * 8 + t + 4][warp * 16 + g + 8];
    }
    // No block sync needed: each warp only reads/writes its own 16 q-columns
    // of Ps from here on.

    float m0r = -1e30f, m1r = -1e30f, l0 = 0.f, l1 = 0.f;
    float oa[8][4] = {};

    for (int kt = 0; kt < TT / 64; ++kt) {
        int buf = kt & 1;

        // S = Qs @ K^T
        float s[8][4] = {};
#pragma unroll
        for (int ks = 0; ks < 8; ++ks) {
#pragma unroll
            for (int nt = 0; nt < 8; ++nt) {
                unsigned bf[2] = {Ks[buf][ks * 8 + t][nt * 8 + g],
                                  Ks[buf][ks * 8 + t + 4][nt * 8 + g]};
                mma8(s[nt], qa[ks], bf);
            }
        }

        // prefetch next K/V tile (safe: all warps passed last iter's sync,
        // they read buf != buf^1)
        if (kt + 1 < TT / 64) {
            int nb2 = buf ^ 1;
#pragma unroll
            for (int i = 0; i < 4; ++i) {
                int j = tid + 256 * i;
                int row = j >> 4, seg = j & 15;
                cpa16(&Ks[nb2][row][seg * 4],
                      Kg + (size_t)row * TT + (kt + 1) * 64 + seg * 4);
                cpa16(&Vs[nb2][row][seg * 4],
                      Vg + (size_t)((kt + 1) * 64 + row) * OUT_C + seg * 4);
            }
            cp_commit();
        }

        // online softmax
        float tm0 = -1e30f, tm1 = -1e30f;
#pragma unroll
        for (int nt = 0; nt < 8; ++nt) {
            tm0 = fmaxf(tm0, fmaxf(s[nt][0], s[nt][1]));
            tm1 = fmaxf(tm1, fmaxf(s[nt][2], s[nt][3]));
        }
        tm0 = fmaxf(tm0, __shfl_xor_sync(0xffffffffu, tm0, 1));
        tm0 = fmaxf(tm0, __shfl_xor_sync(0xffffffffu, tm0, 2));
        tm1 = fmaxf(tm1, __shfl_xor_sync(0xffffffffu, tm1, 1));
        tm1 = fmaxf(tm1, __shfl_xor_sync(0xffffffffu, tm1, 2));
        float mn0 = fmaxf(m0r, tm0), mn1 = fmaxf(m1r, tm1);
        float al0 = __expf(m0r - mn0), al1 = __expf(m1r - mn1);
        m0r = mn0; m1r = mn1;
        float rs0 = 0.f, rs1 = 0.f;
#pragma unroll
        for (int nt = 0; nt < 8; ++nt) {
            s[nt][0] = __expf(s[nt][0] - mn0); rs0 += s[nt][0];
            s[nt][1] = __expf(s[nt][1] - mn0); rs0 += s[nt][1];
            s[nt][2] = __expf(s[nt][2] - mn1); rs1 += s[nt][2];
            s[nt][3] = __expf(s[nt][3] - mn1); rs1 += s[nt][3];
        }
        rs0 += __shfl_xor_sync(0xffffffffu, rs0, 1);
        rs0 += __shfl_xor_sync(0xffffffffu, rs0, 2);
        rs1 += __shfl_xor_sync(0xffffffffu, rs1, 1);
        rs1 += __shfl_xor_sync(0xffffffffu, rs1, 2);
        l0 = l0 * al0 + rs0;
        l1 = l1 * al1 + rs1;
#pragma unroll
        for (int dn = 0; dn < 8; ++dn) {
            oa[dn][0] *= al0; oa[dn][1] *= al0;
            oa[dn][2] *= al1; oa[dn][3] *= al1;
        }

        // P -> warp-private columns of Ps
#pragma unroll
        for (int nt = 0; nt < 8; ++nt) {
            Ps[nt * 8 + 2 * t][warp * 16 + g]         = f2tf(s[nt][0]);
            Ps[nt * 8 + 2 * t + 1][warp * 16 + g]     = f2tf(s[nt][1]);
            Ps[nt * 8 + 2 * t][warp * 16 + g + 8]     = f2tf(s[nt][2]);
            Ps[nt * 8 + 2 * t + 1][warp * 16 + g + 8] = f2tf(s[nt][3]);
        }
        __syncwarp();

        // O += P @ V
#pragma unroll
        for (int ks = 0; ks < 8; ++ks) {
            unsigned pa[4] = {Ps[ks * 8 + t][warp * 16 + g],
                              Ps[ks * 8 + t][warp * 16 + g + 8],
                              Ps[ks * 8 + t + 4][warp * 16 + g],
                              Ps[ks * 8 + t + 4][warp * 16 + g + 8]};
#pragma unroll
            for (int dn = 0; dn < 8; ++dn) {
                unsigned bf[2] = {Vs[buf][ks * 8 + t][dn * 8 + g],
                                  Vs[buf][ks * 8 + t + 4][dn * 8 + g]};
                mma8(oa[dn], pa, bf);
            }
        }

        if (kt + 1 < TT / 64) cp_wait<0>();
        __syncthreads();
    }

    float i0 = 1.f / l0, i1 = 1.f / l1;
    int row0 = q0 + warp * 16 + g;
#pragma unroll
    for (int dn = 0; dn < 8; ++dn) {
        int col = dn * 8 + 2 * t;
        *(float2*)&Op[(size_t)row0 * OUT_C + col] =
            make_float2(oa[dn][0] * i0, oa[dn][1] * i0);
        *(float2*)&Op[(size_t)(row0 + 8) * OUT_C + col] =
            make_float2(oa[dn][2] * i1, oa[dn][3] * i1);
    }
}

// ---------------- mix + LayerNorm (emits tf32 for fc) ------------------------
__global__ __launch_bounds__(256) void mixln_kernel(
    const float* __restrict__ wmix, const float* __restrict__ ln_g,
    const float* __restrict__ ln_b)
{
    int row = blockIdx.x;
    const float* a0 = &g_att[0][0][0][0] + (size_t)row * OUT_C;
    const float* a1 = &g_att[1][0][0][0] + (size_t)row * OUT_C;
    float wm = *wmix;
    int tid = threadIdx.x;

    float v[8];
    float sum = 0.f, sq = 0.f;
#pragma unroll
    for (int k = 0; k < 8; ++k) {
        int c = tid + k * 256;
        float x = a1[c] * wm + a0[c] * (1.f - wm);
        v[k] = x; sum += x; sq += x * x;
    }
#pragma unroll
    for (int off = 16; off; off >>= 1) {
        sum += __shfl_xor_sync(0xffffffffu, sum, off);
        sq  += __shfl_xor_sync(0xffffffffu, sq,  off);
    }
    __shared__ float red[2][8];
    if ((tid & 31) == 0) { red[0][tid >> 5] = sum; red[1][tid >> 5] = sq; }
    __syncthreads();
    float ts = 0.f, t2 = 0.f;
#pragma unroll
    for (int w2 = 0; w2 < 8; ++w2) { ts += red[0][w2]; t2 += red[1][w2]; }
    float mu   = ts * (1.f / 2048.f);
    float var  = t2 * (1.f / 2048.f) - mu * mu;
    float rstd = rsqrtf(var + 1e-5f);
#pragma unroll
    for (int k = 0; k < 8; ++k) {
        int c = tid + k * 256;
        g_rtf[row][c] = f2tf((v[k] - mu) * rstd * ln_g[c] + ln_b[c]);
    }
}

// ---------------- FC GEMM: cp.async 4-stage; fused transposed epilogue -------
// out[b][o][t] written directly (no separate transpose kernel).
__global__ __launch_bounds__(256, 2) void fc_gemm_tc(
    const float* __restrict__ bfc, float* __restrict__ out)
{
    extern __shared__ unsigned sm[];
    unsigned (*A2)[128][20] = (unsigned(*)[128][20])sm;               // [4][128][20]
    unsigned (*Bs)[16][136] = (unsigned(*)[16][136])(sm + 4 * 128 * 20);

    const unsigned* A  = &g_rtf[0][0];
    const unsigned* Wt = &g_wfct[0][0];

    int tid  = threadIdx.x;
    int warp = tid >> 5, lane = tid & 31;
    int g = lane >> 2, t = lane & 3;
    int wm = warp >> 2, wn = warp & 3;
    int m0 = blockIdx.y * 128;
    int n0 = blockIdx.x * 128;

    int ar  = tid & 127;
    int akk = (tid >> 7) << 3;
    int sk  = tid >> 4;
    int sc  = (tid & 15) << 3;

    float acc[4][4][4] = {};

    const int NT = OUT_C / 16;
#pragma unroll
    for (int st = 0; st < 3; ++st) {
        const unsigned* ap  = A  + (size_t)(m0 + ar) * OUT_C + st * 16 + akk;
        const unsigned* bp2 = Wt + (size_t)(st * 16 + sk) * OUT_C + n0 + sc;
        cpa16(&A2[st][ar][akk], ap);   cpa16(&A2[st][ar][akk + 4], ap + 4);
        cpa16(&Bs[st][sk][sc], bp2);   cpa16(&Bs[st][sk][sc + 4], bp2 + 4);
        cp_commit();
    }

    for (int kt = 0; kt < NT; ++kt) {
        if (kt >= NT - 3) cp_wait<0>(); else cp_wait<2>();
        __syncthreads();
        int cur = kt & 3;
#pragma unroll
        for (int kk = 0; kk < 2; ++kk) {
            int k0 = kk * 8;
            unsigned af[4][4], bf[4][2];
#pragma unroll
            for (int mi = 0; mi < 4; ++mi) {
                int m = wm * 64 + mi * 16 + g;
                af[mi][0] = A2[cur][m][k0 + t];
                af[mi][1] = A2[cur][m + 8][k0 + t];
                af[mi][2] = A2[cur][m][k0 + t + 4];
                af[mi][3] = A2[cur][m + 8][k0 + t + 4];
            }
#pragma unroll
            for (int ni = 0; ni < 4; ++ni) {
                int n = wn * 32 + ni * 8 + g;
                bf[ni][0] = Bs[cur][k0 + t][n];
                bf[ni][1] = Bs[cur][k0 + t + 4][n];
            }
#pragma unroll
            for (int mi = 0; mi < 4; ++mi)
#pragma unroll
                for (int ni = 0; ni < 4; ++ni)
                    mma8(acc[mi][ni], af[mi], bf[ni]);
        }
        if (kt + 3 < NT) {
            int st = (kt + 3) & 3;
            int kb = (kt + 3) * 16;
            const unsigned* ap  = A  + (size_t)(m0 + ar) * OUT_C + kb + akk;
            const unsigned* bp2 = Wt + (size_t)(kb + sk) * OUT_C + n0 + sc;
            cpa16(&A2[st][ar][akk], ap);  cpa16(&A2[st][ar][akk + 4], ap + 4);
            cpa16(&Bs[st][sk][sc], bp2);  cpa16(&Bs[st][sk][sc + 4], bp2 + 4);
            cp_commit();
        }
    }

    // ---- fused transposed epilogue: out[b][o][t], 32 o-cols per chunk ----
    __syncthreads();
    float* S = (float*)sm;                 // [32][132]
    int b_out = m0 >> 10;
    int tbase = m0 & 1023;
#pragma unroll
    for (int c = 0; c < 4; ++c) {
        if (wn == c) {
#pragma unroll
            for (int mi = 0; mi < 4; ++mi) {
#pragma unroll
                for (int ni = 0; ni < 4; ++ni) {
                    int srow = ni * 8 + 2 * t;
                    int m = wm * 64 + mi * 16 + g;
                    float b0 = bfc[n0 + 32 * c + srow];
                    float b1 = bfc[n0 + 32 * c + srow + 1];
                    S[srow * 132 + m]           = acc[mi][ni][0] + b0;
                    S[(srow + 1) * 132 + m]     = acc[mi][ni][1] + b1;
                    S[srow * 132 + m + 8]       = acc[mi][ni][2] + b0;
                    S[(srow + 1) * 132 + m + 8] = acc[mi][ni][3] + b1;
                }
            }
        }
        __syncthreads();
        int row = tid >> 3;
        int cseg = (tid & 7) * 16;
        int o = n0 + 32 * c + row;
        float* dst = &out[((size_t)b_out * OUT_C + o) * TT + tbase + cseg];
        const float* src = &S[row * 132 + cseg];
        *(float4*)(dst)      = *(const float4*)(src);
        *(float4*)(dst + 4)  = *(const float4*)(src + 4);
        *(float4*)(dst + 8)  = *(const float4*)(src + 8);
        *(float4*)(dst + 12) = *(const float4*)(src + 12);
        __syncthreads();
    }
}

// ---------------- launch ----------------------------------------------------
extern "C" void kernel_launch(void* const* d_in, const int* in_sizes, int n_in,
                              void* d_out, int out_size)
{
    const float* x_cnn = (const float*)d_in[0];
    const float* x_vit = (const float*)d_in[1];
    const float* Wq    = (const float*)d_in[2];
    const float* bq    = (const float*)d_in[3];
    const float* Wk    = (const float*)d_in[4];
    const float* bk    = (const float*)d_in[5];
    const float* Wv    = (const float*)d_in[6];
    const float* bv    = (const float*)d_in[7];
    const float* w_mix = (const float*)d_in[8];
    const float* ln_g  = (const float*)d_in[9];
    const float* ln_b  = (const float*)d_in[10];
    const float* Wfc   = (const float*)d_in[11];
    const float* bfc   = (const float*)d_in[12];
    float* out = (float*)d_out;

    const int ATT_SMEM  = (64 * 136 + 4 * 64 * 72) * (int)sizeof(unsigned);   // 108544
    const int PROJ_SMEM = 4 * 2 * 16 * 136 * (int)sizeof(unsigned);           // 69632
    const int FC_SMEM   = (4 * 128 * 20 + 4 * 16 * 136) * (int)sizeof(unsigned); // 75776
    cudaFuncSetAttribute(attn_tc,      cudaFuncAttributeMaxDynamicSharedMemorySize, ATT_SMEM);
    cudaFuncSetAttribute(proj_gemm_tc, cudaFuncAttributeMaxDynamicSharedMemorySize, PROJ_SMEM);
    cudaFuncSetAttribute(fc_gemm_tc,   cudaFuncAttributeMaxDynamicSharedMemorySize, FC_SMEM);

    unsigned* xtf  = 0;  cudaGetSymbolAddress((void**)&xtf,  g_xtf);
    unsigned* wt   = 0;  cudaGetSymbolAddress((void**)&wt,   g_wt);
    unsigned* wfct = 0;  cudaGetSymbolAddress((void**)&wfct, g_wfct);

    const int NX4 = NB * CC * TT / 4;
    ecvt<<<(NX4 + 255) / 256, 256>>>((const float4*)x_cnn, (uint4*)xtf, NX4);
    ecvt<<<(NX4 + 255) / 256, 256>>>((const float4*)x_vit,
                                     (uint4*)(xtf + (size_t)NB * CC * TT), NX4);
    tcvt<<<dim3(CC / 32, OUT_C / 32), dim3(32, 8)>>>(Wq, wt, OUT_C, CC);
    tcvt<<<dim3(CC / 32, OUT_C / 32), dim3(32, 8)>>>(Wk, wt + (size_t)CC * OUT_C, OUT_C, CC);
    tcvt<<<dim3(CC / 32, OUT_C / 32), dim3(32, 8)>>>(Wv, wt + 2 * (size_t)CC * OUT_C, OUT_C, CC);
    tcvt<<<dim3(OUT_C / 32, OUT_C / 32), dim3(32, 8)>>>(Wfc, wfct, OUT_C, OUT_C);

    proj_gemm_tc<<<dim3(16, 8, 48), 256, PROJ_SMEM>>>(bq, bk, bv);
    attn_tc<<<dim3(8, 32, 16), 256, ATT_SMEM>>>();
    mixln_kernel<<<NB * TT, 256>>>(w_mix, ln_g, ln_b);
    fc_gemm_tc<<<dim3(16, 64), 256, FC_SMEM>>>(bfc, out);
}

// round 12
// speedup vs baseline: 6.9772x; 1.9184x over previous
#include <cuda_runtime.h>
#include <cuda_fp16.h>

#define CC    1024
#define TT    1024
#define OUT_C 2048
#define NB    8
#define NH    32
#define HD    64

// ---------------- scratch (static device globals) ----------------------------
__device__ __half g_q [2][NB][TT][OUT_C];   // Q, fp16, pre-scaled 1/32
__device__ __half g_k [2][NB][TT][OUT_C];   // K, fp16
__device__ __half g_vT[2][NB][OUT_C][TT];   // V transposed, fp16
__device__ float  g_att[2][NB][TT][OUT_C];
__device__ __half g_rh[NB * TT][OUT_C];     // LN output, fp16
__device__ __half g_xT[2][NB][TT][CC];      // inputs transposed to [t][c], fp16
__device__ __half g_w[3][OUT_C][CC];        // Wq/Wk/Wv, fp16 (native layout)
__device__ __half g_wfc[OUT_C][OUT_C];      // Wfc, fp16 (native layout)

// ---------------- helpers ----------------------------------------------------
__device__ __forceinline__ unsigned packh2(float lo, float hi) {
    __half2 h = __floats2half2_rn(lo, hi);
    return *(unsigned*)&h;
}

__device__ __forceinline__ void mma16(float* d, const unsigned* a, const unsigned* b) {
    asm volatile(
        "mma.sync.aligned.m16n8k16.row.col.f32.f16.f16.f32 "
        "{%0,%1,%2,%3}, {%4,%5,%6,%7}, {%8,%9}, {%0,%1,%2,%3};"
        : "+f"(d[0]), "+f"(d[1]), "+f"(d[2]), "+f"(d[3])
        : "r"(a[0]), "r"(a[1]), "r"(a[2]), "r"(a[3]), "r"(b[0]), "r"(b[1]));
}

__device__ __forceinline__ void cpa16(void* d, const void* s) {
    unsigned sa = (unsigned)__cvta_generic_to_shared(d);
    asm volatile("cp.async.cg.shared.global [%0], [%1], 16;" :: "r"(sa), "l"(s));
}
__device__ __forceinline__ void cp_commit() {
    asm volatile("cp.async.commit_group;");
}
template <int N> __device__ __forceinline__ void cp_wait() {
    asm volatile("cp.async.wait_group %0;" :: "n"(N));
}

// ---------------- prolog converts --------------------------------------------
// 8 floats -> 8 halves per thread
__global__ void ecvt8(const float4* __restrict__ src, uint4* __restrict__ dst, int n8)
{
    int i = blockIdx.x * blockDim.x + threadIdx.x;
    if (i < n8) {
        float4 a = src[2 * i], b = src[2 * i + 1];
        dst[i] = make_uint4(packh2(a.x, a.y), packh2(a.z, a.w),
                            packh2(b.x, b.y), packh2(b.z, b.w));
    }
}

// batched transpose-convert: x[(s,b)][C][T] -> g_xT[s][b][T][C] fp16
__global__ void btcvt(const float* __restrict__ xc, const float* __restrict__ xv)
{
    __shared__ float tile[32][33];
    int z = blockIdx.z;
    int s = z >> 3, b = z & 7;
    const float* src = (s ? xv : xc) + (size_t)b * CC * TT;   // [C][T]
    __half* dst = &g_xT[s][b][0][0];                          // [T][C]
    int t0 = blockIdx.x * 32, c0 = blockIdx.y * 32;
    int tx = threadIdx.x, ty = threadIdx.y;   // (32, 8)
#pragma unroll
    for (int i = 0; i < 4; ++i)
        tile[ty + i * 8][tx] = src[(size_t)(c0 + ty + i * 8) * TT + t0 + tx];
    __syncthreads();
#pragma unroll
    for (int i = 0; i < 4; ++i)
        dst[(size_t)(t0 + ty + i * 8) * CC + c0 + tx] =
            __float2half_rn(tile[tx][ty + i * 8]);
}

// ---------------- GEMM core (fp16 m16n8k16, cp.async 4-stage) ----------------
// A [M][K] row-major fp16, B [N][K] row-major fp16, block tile 128x128, Kt=32.
// smem rows padded to 40 halves (20 words: banks 20g+t all distinct).
#define GST (128 * 40)   // halves per tile (A or B) per stage

__device__ __forceinline__ void g_stage(__half* sm, int stage, int tid,
                                        const __half* Ag, const __half* Bg,
                                        int m0, int n0, int c, int kld) {
    __half* sA = sm + stage * 2 * GST;
    __half* sB = sA + GST;
#pragma unroll
    for (int i = 0; i < 2; ++i) {
        int j = tid + 256 * i;
        int row = j >> 2, seg = j & 3;
        cpa16(sA + row * 40 + seg * 8, Ag + (size_t)(m0 + row) * kld + c * 32 + seg * 8);
    }
#pragma unroll
    for (int i = 0; i < 2; ++i) {
        int j = tid + 256 * i;
        int row = j >> 2, seg = j & 3;
        cpa16(sB + row * 40 + seg * 8, Bg + (size_t)(n0 + row) * kld + c * 32 + seg * 8);
    }
    cp_commit();
}

__device__ __forceinline__ void g_mainloop(__half* sm, float (*acc)[4][4],
                                           int tid, int wm, int wn, int g, int t,
                                           const __half* Ag, const __half* Bg,
                                           int m0, int n0, int kld, int NT) {
    g_stage(sm, 0, tid, Ag, Bg, m0, n0, 0, kld);
    g_stage(sm, 1, tid, Ag, Bg, m0, n0, 1, kld);
    g_stage(sm, 2, tid, Ag, Bg, m0, n0, 2, kld);

    for (int kt = 0; kt < NT; ++kt) {
        if (kt >= NT - 3) cp_wait<0>(); else cp_wait<2>();
        __syncthreads();
        const __half* sA = sm + (kt & 3) * 2 * GST;
        const __half* sB = sA + GST;
#pragma unroll
        for (int kk = 0; kk < 2; ++kk) {
            unsigned af[4][4], bf[4][2];
#pragma unroll
            for (int mi = 0; mi < 4; ++mi) {
                int m = wm * 64 + mi * 16 + g;
                const __half* p0 = sA + m * 40 + kk * 16 + 2 * t;
                af[mi][0] = *(const unsigned*)(p0);
                af[mi][1] = *(const unsigned*)(p0 + 8 * 40);
                af[mi][2] = *(const unsigned*)(p0 + 8);
                af[mi][3] = *(const unsigned*)(p0 + 8 * 40 + 8);
            }
#pragma unroll
            for (int ni = 0; ni < 4; ++ni) {
                int n = wn * 32 + ni * 8 + g;
                const __half* p0 = sB + n * 40 + kk * 16 + 2 * t;
                bf[ni][0] = *(const unsigned*)(p0);
                bf[ni][1] = *(const unsigned*)(p0 + 8);
            }
#pragma unroll
            for (int mi = 0; mi < 4; ++mi)
#pragma unroll
                for (int ni = 0; ni < 4; ++ni)
                    mma16(acc[mi][ni], af[mi], bf[ni]);
        }
        if (kt + 3 < NT)
            g_stage(sm, (kt + 3) & 3, tid, Ag, Bg, m0, n0, kt + 3, kld);
    }
}

// ---------------- projection GEMM --------------------------------------------
// A = g_xT[s][b] ([T][C]), B = g_w[w] ([OUT][C]).
// Epilogue: Q/K row-major fp16 (Q scaled 1/32); V transposed fp16.
__global__ __launch_bounds__(256, 2) void proj_gemm_h(
    const float* __restrict__ bq, const float* __restrict__ bk2,
    const float* __restrict__ bv)
{
    extern __shared__ __half smh[];
    int z = blockIdx.z;
    int w  = z % 3;
    int sb = z / 3;
    int s = sb >> 3, b = sb & 7;
    const __half* Ag = &g_xT[s][b][0][0];
    const __half* Bg = &g_w[w][0][0];
    const float*  bp = (w == 0) ? bq : ((w == 1) ? bk2 : bv);

    int tid  = threadIdx.x;
    int warp = tid >> 5, lane = tid & 31;
    int g = lane >> 2, t = lane & 3;
    int wm = warp >> 2, wn = warp & 3;
    int m0 = blockIdx.y * 128;
    int n0 = blockIdx.x * 128;

    float acc[4][4][4] = {};
    g_mainloop(smh, acc, tid, wm, wn, g, t, Ag, Bg, m0, n0, CC, CC / 32);

    if (w == 2) {
        __half* Tout = &g_vT[s][b][0][0];   // [o][t]
#pragma unroll
        for (int mi = 0; mi < 4; ++mi) {
#pragma unroll
            for (int ni = 0; ni < 4; ++ni) {
                int row = m0 + wm * 64 + mi * 16 + g;
                int col = n0 + wn * 32 + ni * 8 + 2 * t;
                float b0 = bp[col], b1 = bp[col + 1];
                Tout[(size_t)col * TT + row]           = __float2half_rn(acc[mi][ni][0] + b0);
                Tout[(size_t)(col + 1) * TT + row]     = __float2half_rn(acc[mi][ni][1] + b1);
                Tout[(size_t)col * TT + row + 8]       = __float2half_rn(acc[mi][ni][2] + b0);
                Tout[(size_t)(col + 1) * TT + row + 8] = __float2half_rn(acc[mi][ni][3] + b1);
            }
        }
    } else {
        __half* Rout = (w == 0) ? &g_q[s][b][0][0] : &g_k[s][b][0][0];
        float sc2 = (w == 0) ? 0.03125f : 1.0f;
#pragma unroll
        for (int mi = 0; mi < 4; ++mi) {
#pragma unroll
            for (int ni = 0; ni < 4; ++ni) {
                int row = m0 + wm * 64 + mi * 16 + g;
                int col = n0 + wn * 32 + ni * 8 + 2 * t;
                float b0 = bp[col], b1 = bp[col + 1];
                *(unsigned*)&Rout[(size_t)row * OUT_C + col] =
                    packh2((acc[mi][ni][0] + b0) * sc2, (acc[mi][ni][1] + b1) * sc2);
                *(unsigned*)&Rout[(size_t)(row + 8) * OUT_C + col] =
                    packh2((acc[mi][ni][2] + b0) * sc2, (acc[mi][ni][3] + b1) * sc2);
            }
        }
    }
}

// ---------------- FC GEMM + fused transposed output --------------------------
__global__ __launch_bounds__(256, 2) void fc_gemm_h(
    const float* __restrict__ bfc, float* __restrict__ out)
{
    extern __shared__ __half smh[];
    const __half* Ag = &g_rh[0][0];
    const __half* Bg = &g_wfc[0][0];

    int tid  = threadIdx.x;
    int warp = tid >> 5, lane = tid & 31;
    int g = lane >> 2, t = lane & 3;
    int wm = warp >> 2, wn = warp & 3;
    int m0 = blockIdx.y * 128;
    int n0 = blockIdx.x * 128;

    float acc[4][4][4] = {};
    g_mainloop(smh, acc, tid, wm, wn, g, t, Ag, Bg, m0, n0, OUT_C, OUT_C / 32);

    // fused transposed epilogue: out[b][o][t], 32 o-cols per chunk
    __syncthreads();
    float* S = (float*)smh;                // [32][132]
    int b_out = m0 >> 10;
    int tbase = m0 & 1023;
#pragma unroll
    for (int c = 0; c < 4; ++c) {
        if (wn == c) {
#pragma unroll
            for (int mi = 0; mi < 4; ++mi) {
#pragma unroll
                for (int ni = 0; ni < 4; ++ni) {
                    int srow = ni * 8 + 2 * t;
                    int m = wm * 64 + mi * 16 + g;
                    float b0 = bfc[n0 + 32 * c + srow];
                    float b1 = bfc[n0 + 32 * c + srow + 1];
                    S[srow * 132 + m]           = acc[mi][ni][0] + b0;
                    S[(srow + 1) * 132 + m]     = acc[mi][ni][1] + b1;
                    S[srow * 132 + m + 8]       = acc[mi][ni][2] + b0;
                    S[(srow + 1) * 132 + m + 8] = acc[mi][ni][3] + b1;
                }
            }
        }
        __syncthreads();
        int row = tid >> 3;
        int cseg = (tid & 7) * 16;
        int o = n0 + 32 * c + row;
        float* dst = &out[((size_t)b_out * OUT_C + o) * TT + tbase + cseg];
        const float* src = &S[row * 132 + cseg];
        *(float4*)(dst)      = *(const float4*)(src);
        *(float4*)(dst + 4)  = *(const float4*)(src + 4);
        *(float4*)(dst + 8)  = *(const float4*)(src + 8);
        *(float4*)(dst + 12) = *(const float4*)(src + 12);
        __syncthreads();
    }
}

// ---------------- flash attention: fp16 mma, P register pass-through ----------
// Block = 128 q of one (dir,b,h); warp owns 16 q rows. K/V^T double-buffered
// via cp.async. smem rows padded to 72 halves (36 words: banks 4g+t distinct).
__global__ __launch_bounds__(256, 2) void attn_h()
{
    extern __shared__ __half sma[];
    __half* Qs = sma;                         // [128][72]
    __half* Ks = sma + 128 * 72;              // [2][64][72]
    __half* Vt = sma + 128 * 72 + 2 * 64 * 72;// [2][64][72]  (V^T: rows d, cols key)

    int qt = blockIdx.x, h = blockIdx.y, z = blockIdx.z;
    int dir = z >> 3, b = z & 7;
    int skv = 1 - dir;
    const __half* Qg = &g_q [dir][b][0][h * HD];   // [t][o] slice
    const __half* Kg = &g_k [skv][b][0][h * HD];   // [t][o] slice
    const __half* Vg = &g_vT[skv][b][h * HD][0];   // [o][t] slice
    float*        Op = &g_att[dir][b][0][h * HD];

    int tid  = threadIdx.x;
    int warp = tid >> 5, lane = tid & 31;
    int g = lane >> 2, t = lane & 3;
    int q0 = qt * 128;

    // Q: 128 rows x 64 halves (8 segs)
#pragma unroll
    for (int i = 0; i < 4; ++i) {
        int j = tid + 256 * i;
        int row = j >> 3, seg = j & 7;
        cpa16(Qs + row * 72 + seg * 8, Qg + (size_t)(q0 + row) * OUT_C + seg * 8);
    }
    cp_commit();
    // K0 [64 key][64 d], V0^T [64 d][64 key]
#pragma unroll
    for (int i = 0; i < 2; ++i) {
        int j = tid + 256 * i;
        int row = j >> 3, seg = j & 7;
        cpa16(Ks + row * 72 + seg * 8, Kg + (size_t)row * OUT_C + seg * 8);
        cpa16(Vt + row * 72 + seg * 8, Vg + (size_t)row * TT + seg * 8);
    }
    cp_commit();

    cp_wait<0>();
    __syncthreads();

    unsigned qa[4][4];
#pragma unroll
    for (int kc = 0; kc < 4; ++kc) {
        const __half* p0 = Qs + (warp * 16 + g) * 72 + kc * 16 + 2 * t;
        qa[kc][0] = *(const unsigned*)(p0);
        qa[kc][1] = *(const unsigned*)(p0 + 8 * 72);
        qa[kc][2] = *(const unsigned*)(p0 + 8);
        qa[kc][3] = *(const unsigned*)(p0 + 8 * 72 + 8);
    }

    float m0r = -1e30f, m1r = -1e30f, l0 = 0.f, l1 = 0.f;
    float oa[8][4] = {};

    for (int kt = 0; kt < TT / 64; ++kt) {
        int buf = kt & 1;
        const __half* Kb = Ks + buf * 64 * 72;
        const __half* Vb = Vt + buf * 64 * 72;

        // S = Q @ K^T
        float s[8][4] = {};
#pragma unroll
        for (int kc = 0; kc < 4; ++kc) {
#pragma unroll
            for (int nt = 0; nt < 8; ++nt) {
                const __half* p0 = Kb + (nt * 8 + g) * 72 + kc * 16 + 2 * t;
                unsigned bf[2] = {*(const unsigned*)(p0), *(const unsigned*)(p0 + 8)};
                mma16(s[nt], qa[kc], bf);
            }
        }

        // prefetch next K/V tile into buf^1
        if (kt + 1 < TT / 64) {
            __half* Kn = Ks + (buf ^ 1) * 64 * 72;
            __half* Vn = Vt + (buf ^ 1) * 64 * 72;
#pragma unroll
            for (int i = 0; i < 2; ++i) {
                int j = tid + 256 * i;
                int row = j >> 3, seg = j & 7;
                cpa16(Kn + row * 72 + seg * 8,
                      Kg + (size_t)((kt + 1) * 64 + row) * OUT_C + seg * 8);
                cpa16(Vn + row * 72 + seg * 8,
                      Vg + (size_t)row * TT + (kt + 1) * 64 + seg * 8);
            }
            cp_commit();
        }

        // online softmax
        float tm0 = -1e30f, tm1 = -1e30f;
#pragma unroll
        for (int nt = 0; nt < 8; ++nt) {
            tm0 = fmaxf(tm0, fmaxf(s[nt][0], s[nt][1]));
            tm1 = fmaxf(tm1, fmaxf(s[nt][2], s[nt][3]));
        }
        tm0 = fmaxf(tm0, __shfl_xor_sync(0xffffffffu, tm0, 1));
        tm0 = fmaxf(tm0, __shfl_xor_sync(0xffffffffu, tm0, 2));
        tm1 = fmaxf(tm1, __shfl_xor_sync(0xffffffffu, tm1, 1));
        tm1 = fmaxf(tm1, __shfl_xor_sync(0xffffffffu, tm1, 2));
        float mn0 = fmaxf(m0r, tm0), mn1 = fmaxf(m1r, tm1);
        float al0 = __expf(m0r - mn0), al1 = __expf(m1r - mn1);
        m0r = mn0; m1r = mn1;
        float rs0 = 0.f, rs1 = 0.f;
#pragma unroll
        for (int nt = 0; nt < 8; ++nt) {
            s[nt][0] = __expf(s[nt][0] - mn0); rs0 += s[nt][0];
            s[nt][1] = __expf(s[nt][1] - mn0); rs0 += s[nt][1];
            s[nt][2] = __expf(s[nt][2] - mn1); rs1 += s[nt][2];
            s[nt][3] = __expf(s[nt][3] - mn1); rs1 += s[nt][3];
        }
        rs0 += __shfl_xor_sync(0xffffffffu, rs0, 1);
        rs0 += __shfl_xor_sync(0xffffffffu, rs0, 2);
        rs1 += __shfl_xor_sync(0xffffffffu, rs1, 1);
        rs1 += __shfl_xor_sync(0xffffffffu, rs1, 2);
        l0 = l0 * al0 + rs0;
        l1 = l1 * al1 + rs1;
#pragma unroll
        for (int dn = 0; dn < 8; ++dn) {
            oa[dn][0] *= al0; oa[dn][1] *= al0;
            oa[dn][2] *= al1; oa[dn][3] *= al1;
        }

        // O += P @ V  (P passes through registers: S C-frag == PV A-frag)
#pragma unroll
        for (int j = 0; j < 4; ++j) {
            unsigned pa[4] = {packh2(s[2 * j][0],     s[2 * j][1]),
                              packh2(s[2 * j][2],     s[2 * j][3]),
                              packh2(s[2 * j + 1][0], s[2 * j + 1][1]),
                              packh2(s[2 * j + 1][2], s[2 * j + 1][3])};
#pragma unroll
            for (int dn = 0; dn < 8; ++dn) {
                const __half* p0 = Vb + (dn * 8 + g) * 72 + j * 16 + 2 * t;
                unsigned bf[2] = {*(const unsigned*)(p0), *(const unsigned*)(p0 + 8)};
                mma16(oa[dn], pa, bf);
            }
        }

        if (kt + 1 < TT / 64) cp_wait<0>();
        __syncthreads();
    }

    float i0 = 1.f / l0, i1 = 1.f / l1;
    int row0 = q0 + warp * 16 + g;
#pragma unroll
    for (int dn = 0; dn < 8; ++dn) {
        int col = dn * 8 + 2 * t;
        *(float2*)&Op[(size_t)row0 * OUT_C + col] =
            make_float2(oa[dn][0] * i0, oa[dn][1] * i0);
        *(float2*)&Op[(size_t)(row0 + 8) * OUT_C + col] =
            make_float2(oa[dn][2] * i1, oa[dn][3] * i1);
    }
}

// ---------------- mix + LayerNorm (emits fp16 for fc) ------------------------
__global__ __launch_bounds__(256) void mixln_kernel(
    const float* __restrict__ wmix, const float* __restrict__ ln_g,
    const float* __restrict__ ln_b)
{
    int row = blockIdx.x;
    const float* a0 = &g_att[0][0][0][0] + (size_t)row * OUT_C;
    const float* a1 = &g_att[1][0][0][0] + (size_t)row * OUT_C;
    float wm = *wmix;
    int tid = threadIdx.x;

    float v[8];
    float sum = 0.f, sq = 0.f;
#pragma unroll
    for (int k = 0; k < 8; ++k) {
        int c = tid + k * 256;
        float x = a1[c] * wm + a0[c] * (1.f - wm);
        v[k] = x; sum += x; sq += x * x;
    }
#pragma unroll
    for (int off = 16; off; off >>= 1) {
        sum += __shfl_xor_sync(0xffffffffu, sum, off);
        sq  += __shfl_xor_sync(0xffffffffu, sq,  off);
    }
    __shared__ float red[2][8];
    if ((tid & 31) == 0) { red[0][tid >> 5] = sum; red[1][tid >> 5] = sq; }
    __syncthreads();
    float ts = 0.f, t2 = 0.f;
#pragma unroll
    for (int w2 = 0; w2 < 8; ++w2) { ts += red[0][w2]; t2 += red[1][w2]; }
    float mu   = ts * (1.f / 2048.f);
    float var  = t2 * (1.f / 2048.f) - mu * mu;
    float rstd = rsqrtf(var + 1e-5f);
#pragma unroll
    for (int k = 0; k < 8; ++k) {
        int c = tid + k * 256;
        g_rh[row][c] = __float2half_rn((v[k] - mu) * rstd * ln_g[c] + ln_b[c]);
    }
}

// ---------------- launch ----------------------------------------------------
extern "C" void kernel_launch(void* const* d_in, const int* in_sizes, int n_in,
                              void* d_out, int out_size)
{
    const float* x_cnn = (const float*)d_in[0];
    const float* x_vit = (const float*)d_in[1];
    const float* Wq    = (const float*)d_in[2];
    const float* bq    = (const float*)d_in[3];
    const float* Wk    = (const float*)d_in[4];
    const float* bk    = (const float*)d_in[5];
    const float* Wv    = (const float*)d_in[6];
    const float* bv    = (const float*)d_in[7];
    const float* w_mix = (const float*)d_in[8];
    const float* ln_g  = (const float*)d_in[9];
    const float* ln_b  = (const float*)d_in[10];
    const float* Wfc   = (const float*)d_in[11];
    const float* bfc   = (const float*)d_in[12];
    float* out = (float*)d_out;

    const int GEMM_SMEM = 4 * 2 * GST * (int)sizeof(__half);            // 81920
    const int ATT_SMEM  = (128 * 72 + 4 * 64 * 72) * (int)sizeof(__half); // 55296
    cudaFuncSetAttribute(proj_gemm_h, cudaFuncAttributeMaxDynamicSharedMemorySize, GEMM_SMEM);
    cudaFuncSetAttribute(fc_gemm_h,   cudaFuncAttributeMaxDynamicSharedMemorySize, GEMM_SMEM);
    cudaFuncSetAttribute(attn_h,      cudaFuncAttributeMaxDynamicSharedMemorySize, ATT_SMEM);

    __half* wdev = 0;  cudaGetSymbolAddress((void**)&wdev, g_w);
    __half* wfcd = 0;  cudaGetSymbolAddress((void**)&wfcd, g_wfc);

    // prolog: fp16 conversions (weights native layout; X transposed)
    btcvt<<<dim3(TT / 32, CC / 32, 16), dim3(32, 8)>>>(x_cnn, x_vit);
    const int NW8 = OUT_C * CC / 8;     // 262144
    ecvt8<<<(NW8 + 255) / 256, 256>>>((const float4*)Wq, (uint4*)wdev, NW8);
    ecvt8<<<(NW8 + 255) / 256, 256>>>((const float4*)Wk,
                                      (uint4*)(wdev + (size_t)OUT_C * CC), NW8);
    ecvt8<<<(NW8 + 255) / 256, 256>>>((const float4*)Wv,
                                      (uint4*)(wdev + 2 * (size_t)OUT_C * CC), NW8);
    const int NF8 = OUT_C * OUT_C / 8;  // 524288
    ecvt8<<<(NF8 + 255) / 256, 256>>>((const float4*)Wfc, (uint4*)wfcd, NF8);

    proj_gemm_h<<<dim3(OUT_C / 128, TT / 128, 48), 256, GEMM_SMEM>>>(bq, bk, bv);
    attn_h<<<dim3(8, 32, 16), 256, ATT_SMEM>>>();
    mixln_kernel<<<NB * TT, 256>>>(w_mix, ln_g, ln_b);
    fc_gemm_h<<<dim3(OUT_C / 128, (NB * TT) / 128), 256, GEMM_SMEM>>>(bfc, out);
}

// round 17
// speedup vs baseline: 7.7747x; 1.1143x over previous
#include <cuda_runtime.h>
#include <cuda_fp16.h>

#define CC    1024
#define TT    1024
#define OUT_C 2048
#define NB    8
#define NH    32
#define HD    64

// ---------------- scratch (static device globals) ----------------------------
__device__ __half g_q [2][NB][TT][OUT_C];   // Q, fp16, pre-scaled 1/32
__device__ __half g_k [2][NB][TT][OUT_C];   // K, fp16
__device__ __half g_vT[2][NB][OUT_C][TT];   // V transposed, fp16
__device__ __half g_att[2][NB][TT][OUT_C];  // attention out, fp16
__device__ __half g_rh[NB * TT][OUT_C];     // LN output, fp16
__device__ __half g_xT[2][NB][TT][CC];      // inputs transposed to [t][c], fp16
__device__ __half g_w[3][OUT_C][CC];        // Wq/Wk/Wv, fp16 (native layout)
__device__ __half g_wfc[OUT_C][OUT_C];      // Wfc, fp16 (native layout)

// ---------------- helpers ----------------------------------------------------
__device__ __forceinline__ unsigned packh2(float lo, float hi) {
    __half2 h = __floats2half2_rn(lo, hi);
    return *(unsigned*)&h;
}

__device__ __forceinline__ void mma16(float* d, const unsigned* a, const unsigned* b) {
    asm volatile(
        "mma.sync.aligned.m16n8k16.row.col.f32.f16.f16.f32 "
        "{%0,%1,%2,%3}, {%4,%5,%6,%7}, {%8,%9}, {%0,%1,%2,%3};"
        : "+f"(d[0]), "+f"(d[1]), "+f"(d[2]), "+f"(d[3])
        : "r"(a[0]), "r"(a[1]), "r"(a[2]), "r"(a[3]), "r"(b[0]), "r"(b[1]));
}

__device__ __forceinline__ void ldsm4(unsigned& r0, unsigned& r1, unsigned& r2,
                                      unsigned& r3, unsigned addr) {
    asm volatile("ldmatrix.sync.aligned.m8n8.x4.shared.b16 {%0,%1,%2,%3}, [%4];"
                 : "=r"(r0), "=r"(r1), "=r"(r2), "=r"(r3) : "r"(addr));
}

__device__ __forceinline__ void cpa16(void* d, const void* s) {
    unsigned sa = (unsigned)__cvta_generic_to_shared(d);
    asm volatile("cp.async.cg.shared.global [%0], [%1], 16;" :: "r"(sa), "l"(s));
}
__device__ __forceinline__ void cp_commit() {
    asm volatile("cp.async.commit_group;");
}
template <int N> __device__ __forceinline__ void cp_wait() {
    asm volatile("cp.async.wait_group %0;" :: "n"(N));
}

// ---------------- prolog converts --------------------------------------------
__global__ void ecvt8(const float4* __restrict__ src, uint4* __restrict__ dst, int n8)
{
    int i = blockIdx.x * blockDim.x + threadIdx.x;
    if (i < n8) {
        float4 a = src[2 * i], b = src[2 * i + 1];
        dst[i] = make_uint4(packh2(a.x, a.y), packh2(a.z, a.w),
                            packh2(b.x, b.y), packh2(b.z, b.w));
    }
}

__global__ void btcvt(const float* __restrict__ xc, const float* __restrict__ xv)
{
    __shared__ float tile[32][33];
    int z = blockIdx.z;
    int s = z >> 3, b = z & 7;
    const float* src = (s ? xv : xc) + (size_t)b * CC * TT;   // [C][T]
    __half* dst = &g_xT[s][b][0][0];                          // [T][C]
    int t0 = blockIdx.x * 32, c0 = blockIdx.y * 32;
    int tx = threadIdx.x, ty = threadIdx.y;   // (32, 8)
#pragma unroll
    for (int i = 0; i < 4; ++i)
        tile[ty + i * 8][tx] = src[(size_t)(c0 + ty + i * 8) * TT + t0 + tx];
    __syncthreads();
#pragma unroll
    for (int i = 0; i < 4; ++i)
        dst[(size_t)(t0 + ty + i * 8) * CC + c0 + tx] =
            __float2half_rn(tile[tx][ty + i * 8]);
}

// ---------------- GEMM core (fp16 m16n8k16, ldmatrix, cp.async 4-stage) ------
#define GST (128 * 40)   // halves per tile (A or B) per stage

__device__ __forceinline__ void g_stage(__half* sm, int stage, int tid,
                                        const __half* Ag, const __half* Bg,
                                        int m0, int n0, int c, int kld) {
    __half* sA = sm + stage * 2 * GST;
    __half* sB = sA + GST;
#pragma unroll
    for (int i = 0; i < 2; ++i) {
        int j = tid + 256 * i;
        int row = j >> 2, seg = j & 3;
        cpa16(sA + row * 40 + seg * 8, Ag + (size_t)(m0 + row) * kld + c * 32 + seg * 8);
    }
#pragma unroll
    for (int i = 0; i < 2; ++i) {
        int j = tid + 256 * i;
        int row = j >> 2, seg = j & 3;
        cpa16(sB + row * 40 + seg * 8, Bg + (size_t)(n0 + row) * kld + c * 32 + seg * 8);
    }
    cp_commit();
}

__device__ __forceinline__ void g_mainloop(__half* sm, float (*acc)[4][4],
                                           int tid, int wm, int wn, int lane,
                                           const __half* Ag, const __half* Bg,
                                           int m0, int n0, int kld, int NT) {
    int lane8 = lane & 7, lgrp = lane >> 3;
    // ldmatrix lane->row/col maps (in halves)
    int a_row = wm * 64 + (lgrp & 1) * 8 + lane8;
    int a_col = (lgrp >> 1) * 8;
    int b_row = wn * 32 + (lgrp >> 1) * 8 + lane8;
    int b_col = (lgrp & 1) * 8;
    unsigned smu = (unsigned)__cvta_generic_to_shared(sm);

    g_stage(sm, 0, tid, Ag, Bg, m0, n0, 0, kld);
    g_stage(sm, 1, tid, Ag, Bg, m0, n0, 1, kld);
    g_stage(sm, 2, tid, Ag, Bg, m0, n0, 2, kld);

    for (int kt = 0; kt < NT; ++kt) {
        if (kt >= NT - 3) cp_wait<0>(); else cp_wait<2>();
        __syncthreads();
        unsigned sAu = smu + (unsigned)(kt & 3) * 2 * GST * 2;
        unsigned sBu = sAu + GST * 2;
#pragma unroll
        for (int kk = 0; kk < 2; ++kk) {
            int kcol = kk * 16;
            unsigned af[4][4], bf[4][2];
#pragma unroll
            for (int mi = 0; mi < 4; ++mi)
                ldsm4(af[mi][0], af[mi][1], af[mi][2], af[mi][3],
                      sAu + 2u * ((a_row + mi * 16) * 40 + kcol + a_col));
#pragma unroll
            for (int p = 0; p < 2; ++p)
                ldsm4(bf[2 * p][0], bf[2 * p][1], bf[2 * p + 1][0], bf[2 * p + 1][1],
                      sBu + 2u * ((b_row + p * 16) * 40 + kcol + b_col));
#pragma unroll
            for (int mi = 0; mi < 4; ++mi)
#pragma unroll
                for (int ni = 0; ni < 4; ++ni)
                    mma16(acc[mi][ni], af[mi], bf[ni]);
        }
        if (kt + 3 < NT)
            g_stage(sm, (kt + 3) & 3, tid, Ag, Bg, m0, n0, kt + 3, kld);
    }
}

// ---------------- projection GEMM --------------------------------------------
__global__ __launch_bounds__(256, 2) void proj_gemm_h(
    const float* __restrict__ bq, const float* __restrict__ bk2,
    const float* __restrict__ bv)
{
    extern __shared__ __half smh[];
    int z = blockIdx.z;
    int w  = z % 3;
    int sb = z / 3;
    int s = sb >> 3, b = sb & 7;
    const __half* Ag = &g_xT[s][b][0][0];
    const __half* Bg = &g_w[w][0][0];
    const float*  bp = (w == 0) ? bq : ((w == 1) ? bk2 : bv);

    int tid  = threadIdx.x;
    int warp = tid >> 5, lane = tid & 31;
    int g = lane >> 2, t = lane & 3;
    int wm = warp >> 2, wn = warp & 3;
    int m0 = blockIdx.y * 128;
    int n0 = blockIdx.x * 128;

    float acc[4][4][4] = {};
    g_mainloop(smh, acc, tid, wm, wn, lane, Ag, Bg, m0, n0, CC, CC / 32);

    if (w == 2) {
        __half* Tout = &g_vT[s][b][0][0];   // [o][t]
#pragma unroll
        for (int mi = 0; mi < 4; ++mi) {
#pragma unroll
            for (int ni = 0; ni < 4; ++ni) {
                int row = m0 + wm * 64 + mi * 16 + g;
                int col = n0 + wn * 32 + ni * 8 + 2 * t;
                float b0 = bp[col], b1 = bp[col + 1];
                Tout[(size_t)col * TT + row]           = __float2half_rn(acc[mi][ni][0] + b0);
                Tout[(size_t)(col + 1) * TT + row]     = __float2half_rn(acc[mi][ni][1] + b1);
                Tout[(size_t)col * TT + row + 8]       = __float2half_rn(acc[mi][ni][2] + b0);
                Tout[(size_t)(col + 1) * TT + row + 8] = __float2half_rn(acc[mi][ni][3] + b1);
            }
        }
    } else {
        __half* Rout = (w == 0) ? &g_q[s][b][0][0] : &g_k[s][b][0][0];
        float sc2 = (w == 0) ? 0.03125f : 1.0f;
#pragma unroll
        for (int mi = 0; mi < 4; ++mi) {
#pragma unroll
            for (int ni = 0; ni < 4; ++ni) {
                int row = m0 + wm * 64 + mi * 16 + g;
                int col = n0 + wn * 32 + ni * 8 + 2 * t;
                float b0 = bp[col], b1 = bp[col + 1];
                *(unsigned*)&Rout[(size_t)row * OUT_C + col] =
                    packh2((acc[mi][ni][0] + b0) * sc2, (acc[mi][ni][1] + b1) * sc2);
                *(unsigned*)&Rout[(size_t)(row + 8) * OUT_C + col] =
                    packh2((acc[mi][ni][2] + b0) * sc2, (acc[mi][ni][3] + b1) * sc2);
            }
        }
    }
}

// ---------------- FC GEMM + fused transposed output --------------------------
__global__ __launch_bounds__(256, 2) void fc_gemm_h(
    const float* __restrict__ bfc, float* __restrict__ out)
{
    extern __shared__ __half smh[];
    const __half* Ag = &g_rh[0][0];
    const __half* Bg = &g_wfc[0][0];

    int tid  = threadIdx.x;
    int warp = tid >> 5, lane = tid & 31;
    int g = lane >> 2, t = lane & 3;
    int wm = warp >> 2, wn = warp & 3;
    int m0 = blockIdx.y * 128;
    int n0 = blockIdx.x * 128;

    float acc[4][4][4] = {};
    g_mainloop(smh, acc, tid, wm, wn, lane, Ag, Bg, m0, n0, OUT_C, OUT_C / 32);

    __syncthreads();
    float* S = (float*)smh;                // [32][132]
    int b_out = m0 >> 10;
    int tbase = m0 & 1023;
#pragma unroll
    for (int c = 0; c < 4; ++c) {
        if (wn == c) {
#pragma unroll
            for (int mi = 0; mi < 4; ++mi) {
#pragma unroll
                for (int ni = 0; ni < 4; ++ni) {
                    int srow = ni * 8 + 2 * t;
                    int m = wm * 64 + mi * 16 + g;
                    float b0 = bfc[n0 + 32 * c + srow];
                    float b1 = bfc[n0 + 32 * c + srow + 1];
                    S[srow * 132 + m]           = acc[mi][ni][0] + b0;
                    S[(srow + 1) * 132 + m]     = acc[mi][ni][1] + b1;
                    S[srow * 132 + m + 8]       = acc[mi][ni][2] + b0;
                    S[(srow + 1) * 132 + m + 8] = acc[mi][ni][3] + b1;
                }
            }
        }
        __syncthreads();
        int row = tid >> 3;
        int cseg = (tid & 7) * 16;
        int o = n0 + 32 * c + row;
        float* dst = &out[((size_t)b_out * OUT_C + o) * TT + tbase + cseg];
        const float* src = &S[row * 132 + cseg];
        *(float4*)(dst)      = *(const float4*)(src);
        *(float4*)(dst + 4)  = *(const float4*)(src + 4);
        *(float4*)(dst + 8)  = *(const float4*)(src + 8);
        *(float4*)(dst + 12) = *(const float4*)(src + 12);
        __syncthreads();
    }
}

// ---------------- flash attention: fp16 mma + ldmatrix -----------------------
__global__ __launch_bounds__(256, 2) void attn_h()
{
    extern __shared__ __half sma[];
    __half* Qs = sma;                         // [128][72]
    __half* Ks = sma + 128 * 72;              // [2][64][72]
    __half* Vt = sma + 128 * 72 + 2 * 64 * 72;// [2][64][72]

    int qt = blockIdx.x, h = blockIdx.y, z = blockIdx.z;
    int dir = z >> 3, b = z & 7;
    int skv = 1 - dir;
    const __half* Qg = &g_q [dir][b][0][h * HD];
    const __half* Kg = &g_k [skv][b][0][h * HD];
    const __half* Vg = &g_vT[skv][b][h * HD][0];
    __half*       Op = &g_att[dir][b][0][h * HD];

    int tid  = threadIdx.x;
    int warp = tid >> 5, lane = tid & 31;
    int g = lane >> 2, t = lane & 3;
    int lane8 = lane & 7, lgrp = lane >> 3;
    int q0 = qt * 128;

#pragma unroll
    for (int i = 0; i < 4; ++i) {
        int j = tid + 256 * i;
        int row = j >> 3, seg = j & 7;
        cpa16(Qs + row * 72 + seg * 8, Qg + (size_t)(q0 + row) * OUT_C + seg * 8);
    }
    cp_commit();
#pragma unroll
    for (int i = 0; i < 2; ++i) {
        int j = tid + 256 * i;
        int row = j >> 3, seg = j & 7;
        cpa16(Ks + row * 72 + seg * 8, Kg + (size_t)row * OUT_C + seg * 8);
        cpa16(Vt + row * 72 + seg * 8, Vg + (size_t)row * TT + seg * 8);
    }
    cp_commit();

    cp_wait<0>();
    __syncthreads();

    unsigned Qu  = (unsigned)__cvta_generic_to_shared(Qs);
    unsigned Ksu = (unsigned)__cvta_generic_to_shared(Ks);
    unsigned Vtu = (unsigned)__cvta_generic_to_shared(Vt);

    // A-style lane map (Q): row = warp*16 + (lgrp&1)*8 + lane8, col = (lgrp>>1)*8
    int qrow = warp * 16 + (lgrp & 1) * 8 + lane8;
    int qcol = (lgrp >> 1) * 8;
    // B-style lane map (K/V): row = p*16 + (lgrp>>1)*8 + lane8, col = (lgrp&1)*8
    int brow = (lgrp >> 1) * 8 + lane8;
    int bcol = (lgrp & 1) * 8;

    unsigned qa[4][4];
#pragma unroll
    for (int kc = 0; kc < 4; ++kc)
        ldsm4(qa[kc][0], qa[kc][1], qa[kc][2], qa[kc][3],
              Qu + 2u * (qrow * 72 + kc * 16 + qcol));

    float m0r = -1e30f, m1r = -1e30f, l0 = 0.f, l1 = 0.f;
    float oa[8][4] = {};

    for (int kt = 0; kt < TT / 64; ++kt) {
        int buf = kt & 1;
        unsigned Kb = Ksu + (unsigned)buf * 64 * 72 * 2;
        unsigned Vb = Vtu + (unsigned)buf * 64 * 72 * 2;

        // S = Q @ K^T
        float s[8][4] = {};
#pragma unroll
        for (int kc = 0; kc < 4; ++kc) {
#pragma unroll
            for (int p = 0; p < 4; ++p) {
                unsigned b0, b1, b2, b3;
                ldsm4(b0, b1, b2, b3,
                      Kb + 2u * ((p * 16 + brow) * 72 + kc * 16 + bcol));
                unsigned bfa[2] = {b0, b1}, bfb[2] = {b2, b3};
                mma16(s[2 * p],     qa[kc], bfa);
                mma16(s[2 * p + 1], qa[kc], bfb);
            }
        }

        if (kt + 1 < TT / 64) {
            __half* Kn = Ks + (buf ^ 1) * 64 * 72;
            __half* Vn = Vt + (buf ^ 1) * 64 * 72;
#pragma unroll
            for (int i = 0; i < 2; ++i) {
                int j = tid + 256 * i;
                int row = j >> 3, seg = j & 7;
                cpa16(Kn + row * 72 + seg * 8,
                      Kg + (size_t)((kt + 1) * 64 + row) * OUT_C + seg * 8);
                cpa16(Vn + row * 72 + seg * 8,
                      Vg + (size_t)row * TT + (kt + 1) * 64 + seg * 8);
            }
            cp_commit();
        }

        // online softmax
        float tm0 = -1e30f, tm1 = -1e30f;
#pragma unroll
        for (int nt = 0; nt < 8; ++nt) {
            tm0 = fmaxf(tm0, fmaxf(s[nt][0], s[nt][1]));
            tm1 = fmaxf(tm1, fmaxf(s[nt][2], s[nt][3]));
        }
        tm0 = fmaxf(tm0, __shfl_xor_sync(0xffffffffu, tm0, 1));
        tm0 = fmaxf(tm0, __shfl_xor_sync(0xffffffffu, tm0, 2));
        tm1 = fmaxf(tm1, __shfl_xor_sync(0xffffffffu, tm1, 1));
        tm1 = fmaxf(tm1, __shfl_xor_sync(0xffffffffu, tm1, 2));
        float mn0 = fmaxf(m0r, tm0), mn1 = fmaxf(m1r, tm1);
        float al0 = __expf(m0r - mn0), al1 = __expf(m1r - mn1);
        m0r = mn0; m1r = mn1;
        float rs0 = 0.f, rs1 = 0.f;
#pragma unroll
        for (int nt = 0; nt < 8; ++nt) {
            s[nt][0] = __expf(s[nt][0] - mn0); rs0 += s[nt][0];
            s[nt][1] = __expf(s[nt][1] - mn0); rs0 += s[nt][1];
            s[nt][2] = __expf(s[nt][2] - mn1); rs1 += s[nt][2];
            s[nt][3] = __expf(s[nt][3] - mn1); rs1 += s[nt][3];
        }
        rs0 += __shfl_xor_sync(0xffffffffu, rs0, 1);
        rs0 += __shfl_xor_sync(0xffffffffu, rs0, 2);
        rs1 += __shfl_xor_sync(0xffffffffu, rs1, 1);
        rs1 += __shfl_xor_sync(0xffffffffu, rs1, 2);
        l0 = l0 * al0 + rs0;
        l1 = l1 * al1 + rs1;
#pragma unroll
        for (int dn = 0; dn < 8; ++dn) {
            oa[dn][0] *= al0; oa[dn][1] *= al0;
            oa[dn][2] *= al1; oa[dn][3] *= al1;
        }

        // O += P @ V (P in registers)
#pragma unroll
        for (int j = 0; j < 4; ++j) {
            unsigned pa[4] = {packh2(s[2 * j][0],     s[2 * j][1]),
                              packh2(s[2 * j][2],     s[2 * j][3]),
                              packh2(s[2 * j + 1][0], s[2 * j + 1][1]),
                              packh2(s[2 * j + 1][2], s[2 * j + 1][3])};
#pragma unroll
            for (int p = 0; p < 4; ++p) {
                unsigned b0, b1, b2, b3;
                ldsm4(b0, b1, b2, b3,
                      Vb + 2u * ((p * 16 + brow) * 72 + j * 16 + bcol));
                unsigned bfa[2] = {b0, b1}, bfb[2] = {b2, b3};
                mma16(oa[2 * p],     pa, bfa);
                mma16(oa[2 * p + 1], pa, bfb);
            }
        }

        if (kt + 1 < TT / 64) cp_wait<0>();
        __syncthreads();
    }

    float i0 = 1.f / l0, i1 = 1.f / l1;
    int row0 = q0 + warp * 16 + g;
#pragma unroll
    for (int dn = 0; dn < 8; ++dn) {
        int col = dn * 8 + 2 * t;
        *(unsigned*)&Op[(size_t)row0 * OUT_C + col] =
            packh2(oa[dn][0] * i0, oa[dn][1] * i0);
        *(unsigned*)&Op[(size_t)(row0 + 8) * OUT_C + col] =
            packh2(oa[dn][2] * i1, oa[dn][3] * i1);
    }
}

// ---------------- mix + LayerNorm (fp16 in, fp16 out) ------------------------
__global__ __launch_bounds__(256) void mixln_kernel(
    const float* __restrict__ wmix, const float* __restrict__ ln_g,
    const float* __restrict__ ln_b)
{
    int row = blockIdx.x;
    const __half2* a0 = (const __half2*)(&g_att[0][0][0][0] + (size_t)row * OUT_C);
    const __half2* a1 = (const __half2*)(&g_att[1][0][0][0] + (size_t)row * OUT_C);
    __half2* dst = (__half2*)(&g_rh[row][0]);
    float wm = *wmix;
    int tid = threadIdx.x;

    float2 v[4];
    float sum = 0.f, sq = 0.f;
#pragma unroll
    for (int k = 0; k < 4; ++k) {
        int c2 = tid + k * 256;
        float2 f0 = __half22float2(a0[c2]);
        float2 f1 = __half22float2(a1[c2]);
        float vx = f1.x * wm + f0.x * (1.f - wm);
        float vy = f1.y * wm + f0.y * (1.f - wm);
        v[k] = make_float2(vx, vy);
        sum += vx + vy; sq += vx * vx + vy * vy;
    }
#pragma unroll
    for (int off = 16; off; off >>= 1) {
        sum += __shfl_xor_sync(0xffffffffu, sum, off);
        sq  += __shfl_xor_sync(0xffffffffu, sq,  off);
    }
    __shared__ float red[2][8];
    if ((tid & 31) == 0) { red[0][tid >> 5] = sum; red[1][tid >> 5] = sq; }
    __syncthreads();
    float ts = 0.f, t2 = 0.f;
#pragma unroll
    for (int w2 = 0; w2 < 8; ++w2) { ts += red[0][w2]; t2 += red[1][w2]; }
    float mu   = ts * (1.f / 2048.f);
    float var  = t2 * (1.f / 2048.f) - mu * mu;
    float rstd = rsqrtf(var + 1e-5f);
#pragma unroll
    for (int k = 0; k < 4; ++k) {
        int c2 = tid + k * 256;
        float gx = ln_g[2 * c2], gy = ln_g[2 * c2 + 1];
        float bx = ln_b[2 * c2], by = ln_b[2 * c2 + 1];
        dst[c2] = __floats2half2_rn((v[k].x - mu) * rstd * gx + bx,
                                    (v[k].y - mu) * rstd * gy + by);
    }
}

// ---------------- launch ----------------------------------------------------
extern "C" void kernel_launch(void* const* d_in, const int* in_sizes, int n_in,
                              void* d_out, int out_size)
{
    const float* x_cnn = (const float*)d_in[0];
    const float* x_vit = (const float*)d_in[1];
    const float* Wq    = (const float*)d_in[2];
    const float* bq    = (const float*)d_in[3];
    const float* Wk    = (const float*)d_in[4];
    const float* bk    = (const float*)d_in[5];
    const float* Wv    = (const float*)d_in[6];
    const float* bv    = (const float*)d_in[7];
    const float* w_mix = (const float*)d_in[8];
    const float* ln_g  = (const float*)d_in[9];
    const float* ln_b  = (const float*)d_in[10];
    const float* Wfc   = (const float*)d_in[11];
    const float* bfc   = (const float*)d_in[12];
    float* out = (float*)d_out;

    const int GEMM_SMEM = 4 * 2 * GST * (int)sizeof(__half);              // 81920
    const int ATT_SMEM  = (128 * 72 + 4 * 64 * 72) * (int)sizeof(__half); // 55296
    cudaFuncSetAttribute(proj_gemm_h, cudaFuncAttributeMaxDynamicSharedMemorySize, GEMM_SMEM);
    cudaFuncSetAttribute(fc_gemm_h,   cudaFuncAttributeMaxDynamicSharedMemorySize, GEMM_SMEM);
    cudaFuncSetAttribute(attn_h,      cudaFuncAttributeMaxDynamicSharedMemorySize, ATT_SMEM);

    __half* wdev = 0;  cudaGetSymbolAddress((void**)&wdev, g_w);
    __half* wfcd = 0;  cudaGetSymbolAddress((void**)&wfcd, g_wfc);

    btcvt<<<dim3(TT / 32, CC / 32, 16), dim3(32, 8)>>>(x_cnn, x_vit);
    const int NW8 = OUT_C * CC / 8;
    ecvt8<<<(NW8 + 255) / 256, 256>>>((const float4*)Wq, (uint4*)wdev, NW8);
    ecvt8<<<(NW8 + 255) / 256, 256>>>((const float4*)Wk,
                                      (uint4*)(wdev + (size_t)OUT_C * CC), NW8);
    ecvt8<<<(NW8 + 255) / 256, 256>>>((const float4*)Wv,
                                      (uint4*)(wdev + 2 * (size_t)OUT_C * CC), NW8);
    const int NF8 = OUT_C * OUT_C / 8;
    ecvt8<<<(NF8 + 255) / 256, 256>>>((const float4*)Wfc, (uint4*)wfcd, NF8);

    proj_gemm_h<<<dim3(OUT_C / 128, TT / 128, 48), 256, GEMM_SMEM>>>(bq, bk, bv);
    attn_h<<<dim3(8, 32, 16), 256, ATT_SMEM>>>();
    mixln_kernel<<<NB * TT, 256>>>(w_mix, ln_g, ln_b);
    fc_gemm_h<<<dim3(OUT_C / 128, (NB * TT) / 128), 256, GEMM_SMEM>>>(bfc, out);
}